// round 3
// baseline (speedup 1.0000x reference)
#include <cuda_runtime.h>
#include <math_constants.h>

#define NB 4
#define NC 1024
#define NT 1024
#define NH 16
#define NDH 64

// Scratch (allocation-free): q, kv, attention output
__device__ float g_q[NB * NC * NT];        // 16 MB
__device__ float g_kv[NB * 2 * NC * NT];   // 32 MB
__device__ float g_att[NB * NC * NT];      // 16 MB

// ---------------------------------------------------------------------------
// Batched SGEMM with bias: Y[b] = W (MxK) @ X[b] (KxN) + bias
// 128x128 block tile, 8x8 per thread, K-tile 8, 256 threads.
// MODE 0: X = arg,  Y = g_q
// MODE 1: X = arg,  Y = g_kv
// MODE 2: X = g_att, Y = arg (d_out)
// All __device__-symbol addressing happens in device code only.
// ---------------------------------------------------------------------------
template <int MODE>
__global__ __launch_bounds__(256) void sgemm_bias_kernel(
    const float* __restrict__ W, const float* __restrict__ Xarg,
    const float* __restrict__ bias, float* __restrict__ Yarg,
    int M, int K, int N)
{
    __shared__ float As[8][128];
    __shared__ float Bs[8][128];

    const int tid = threadIdx.x;
    const int tx = tid & 15, ty = tid >> 4;
    const int m0 = blockIdx.y * 128;
    const int n0 = blockIdx.x * 128;

    const float* Xbase = (MODE == 2) ? (const float*)g_att : Xarg;
    float* Ybase;
    if (MODE == 0)      Ybase = g_q;
    else if (MODE == 1) Ybase = g_kv;
    else                Ybase = Yarg;

    const float* Xb = Xbase + (size_t)blockIdx.z * K * N;
    float* Yb = Ybase + (size_t)blockIdx.z * M * N;

    const int arow = tid >> 1;          // 0..127
    const int acol = (tid & 1) * 4;     // 0 or 4
    const int brow = tid >> 5;          // 0..7
    const int bcol = (tid & 31) * 4;    // 0..124

    float acc[8][8];
#pragma unroll
    for (int i = 0; i < 8; i++)
#pragma unroll
        for (int j = 0; j < 8; j++) acc[i][j] = 0.f;

    for (int k0 = 0; k0 < K; k0 += 8) {
        float4 av = *(const float4*)&W[(size_t)(m0 + arow) * K + k0 + acol];
        As[acol + 0][arow] = av.x;
        As[acol + 1][arow] = av.y;
        As[acol + 2][arow] = av.z;
        As[acol + 3][arow] = av.w;
        *(float4*)&Bs[brow][bcol] =
            *(const float4*)&Xb[(size_t)(k0 + brow) * N + n0 + bcol];
        __syncthreads();

#pragma unroll
        for (int k = 0; k < 8; k++) {
            float ar[8], br[8];
            *(float4*)&ar[0] = *(const float4*)&As[k][ty * 8];
            *(float4*)&ar[4] = *(const float4*)&As[k][ty * 8 + 4];
            *(float4*)&br[0] = *(const float4*)&Bs[k][tx * 8];
            *(float4*)&br[4] = *(const float4*)&Bs[k][tx * 8 + 4];
#pragma unroll
            for (int i = 0; i < 8; i++)
#pragma unroll
                for (int j = 0; j < 8; j++)
                    acc[i][j] = fmaf(ar[i], br[j], acc[i][j]);
        }
        __syncthreads();
    }

#pragma unroll
    for (int i = 0; i < 8; i++) {
        int m = m0 + ty * 8 + i;
        float bv = bias[m];
        float4 o0 = make_float4(acc[i][0] + bv, acc[i][1] + bv,
                                acc[i][2] + bv, acc[i][3] + bv);
        float4 o1 = make_float4(acc[i][4] + bv, acc[i][5] + bv,
                                acc[i][6] + bv, acc[i][7] + bv);
        *(float4*)&Yb[(size_t)m * N + n0 + tx * 8] = o0;
        *(float4*)&Yb[(size_t)m * N + n0 + tx * 8 + 4] = o1;
    }
}

// ---------------------------------------------------------------------------
// Fused RoPE + flash attention.
// Grid: (T/64 q-blocks, H, B). Block: 256 threads.
// Q tile 64x64 (rows=query t, cols=head dim), K/V tiles 32x64.
// Online softmax state (m, l) per row in smem; O accumulator 4x4 per thread.
// ---------------------------------------------------------------------------
__global__ __launch_bounds__(256) void attn_kernel()
{
    __shared__ float qs[64][65];
    __shared__ float ks[32][65];
    __shared__ float vs[32][65];
    __shared__ float ps[64][33];
    __shared__ float s_m[64], s_l[64], s_alpha[64];

    const int tid = threadIdx.x;
    const int tx = tid & 15, ty = tid >> 4;
    const int b = blockIdx.z, h = blockIdx.y;
    const int q0 = blockIdx.x * 64;

    const float* qg = g_q + (size_t)b * NC * NT + (size_t)h * NDH * NT;
    const float* kg = g_kv + (size_t)b * 2 * NC * NT + (size_t)h * NDH * NT;
    const float* vg = kg + (size_t)NC * NT;

    const float LN1E4_16 = 0.57564627324851145f;  // ln(10000)/16

    // Load Q tile (transposed staging: global [d][t] -> smem [t][d])
    for (int idx = tid; idx < 64 * 64; idx += 256) {
        int d = idx >> 6, t = idx & 63;
        qs[t][d] = qg[(size_t)d * NT + q0 + t];
    }
    if (tid < 64) { s_m[tid] = -CUDART_INF_F; s_l[tid] = 0.f; }
    __syncthreads();

    // RoPE on q (first 32 dims, half-rotation pairs (j, j+16))
    for (int idx = tid; idx < 64 * 16; idx += 256) {
        int t = idx >> 4, j = idx & 15;
        float theta = __expf(-(float)j * LN1E4_16);
        float ang = (float)(q0 + t) * theta;
        float sn, cs;
        sincosf(ang, &sn, &cs);
        float x0 = qs[t][j], x1 = qs[t][j + 16];
        qs[t][j]      = x0 * cs - x1 * sn;
        qs[t][j + 16] = x1 * cs + x0 * sn;
    }

    float O[4][4];
#pragma unroll
    for (int i = 0; i < 4; i++)
#pragma unroll
        for (int j = 0; j < 4; j++) O[i][j] = 0.f;

    __syncthreads();

    for (int k0 = 0; k0 < NT; k0 += 32) {
        // Load K/V tiles
        for (int idx = tid; idx < 32 * 64; idx += 256) {
            int d = idx >> 5, t = idx & 31;
            ks[t][d] = kg[(size_t)d * NT + k0 + t];
            vs[t][d] = vg[(size_t)d * NT + k0 + t];
        }
        __syncthreads();
        // RoPE on k
        for (int idx = tid; idx < 32 * 16; idx += 256) {
            int t = idx >> 4, j = idx & 15;
            float theta = __expf(-(float)j * LN1E4_16);
            float ang = (float)(k0 + t) * theta;
            float sn, cs;
            sincosf(ang, &sn, &cs);
            float x0 = ks[t][j], x1 = ks[t][j + 16];
            ks[t][j]      = x0 * cs - x1 * sn;
            ks[t][j + 16] = x1 * cs + x0 * sn;
        }
        __syncthreads();

        // S = q @ k^T * scale. rows i = ty*4+ii (64), cols j = tx*2+jj (32)
        float sacc[4][2];
#pragma unroll
        for (int ii = 0; ii < 4; ii++) { sacc[ii][0] = 0.f; sacc[ii][1] = 0.f; }
#pragma unroll 16
        for (int d = 0; d < 64; d++) {
            float kv0 = ks[tx * 2][d];
            float kv1 = ks[tx * 2 + 1][d];
#pragma unroll
            for (int ii = 0; ii < 4; ii++) {
                float qv = qs[ty * 4 + ii][d];
                sacc[ii][0] = fmaf(qv, kv0, sacc[ii][0]);
                sacc[ii][1] = fmaf(qv, kv1, sacc[ii][1]);
            }
        }
#pragma unroll
        for (int ii = 0; ii < 4; ii++) {
            ps[ty * 4 + ii][tx * 2]     = sacc[ii][0] * 0.125f;
            ps[ty * 4 + ii][tx * 2 + 1] = sacc[ii][1] * 0.125f;
        }
        __syncthreads();

        // Online softmax per row (one thread per row, 64 active)
        if (tid < 64) {
            int r = tid;
            float mx = -CUDART_INF_F;
#pragma unroll 8
            for (int j = 0; j < 32; j++) mx = fmaxf(mx, ps[r][j]);
            float m_new = fmaxf(s_m[r], mx);
            float alpha = __expf(s_m[r] - m_new);
            float l = s_l[r] * alpha;
#pragma unroll 8
            for (int j = 0; j < 32; j++) {
                float p = __expf(ps[r][j] - m_new);
                ps[r][j] = p;
                l += p;
            }
            s_m[r] = m_new;
            s_l[r] = l;
            s_alpha[r] = alpha;
        }
        __syncthreads();

        // O = O*alpha + P @ V. rows i = ty*4+ii, cols d = tx*4+dd
#pragma unroll
        for (int ii = 0; ii < 4; ii++) {
            float a = s_alpha[ty * 4 + ii];
#pragma unroll
            for (int dd = 0; dd < 4; dd++) O[ii][dd] *= a;
        }
#pragma unroll 8
        for (int j = 0; j < 32; j++) {
            float v0 = vs[j][tx * 4];
            float v1 = vs[j][tx * 4 + 1];
            float v2 = vs[j][tx * 4 + 2];
            float v3 = vs[j][tx * 4 + 3];
#pragma unroll
            for (int ii = 0; ii < 4; ii++) {
                float p = ps[ty * 4 + ii][j];
                O[ii][0] = fmaf(p, v0, O[ii][0]);
                O[ii][1] = fmaf(p, v1, O[ii][1]);
                O[ii][2] = fmaf(p, v2, O[ii][2]);
                O[ii][3] = fmaf(p, v3, O[ii][3]);
            }
        }
        __syncthreads();
    }

    // Normalize and write out via smem (coalesced transposed store)
#pragma unroll
    for (int ii = 0; ii < 4; ii++) {
        float inv_l = 1.f / s_l[ty * 4 + ii];
#pragma unroll
        for (int dd = 0; dd < 4; dd++)
            qs[ty * 4 + ii][tx * 4 + dd] = O[ii][dd] * inv_l;
    }
    __syncthreads();
    float* og = g_att + (size_t)b * NC * NT + (size_t)h * NDH * NT;
    for (int idx = tid; idx < 64 * 64; idx += 256) {
        int d = idx >> 6, t = idx & 63;
        og[(size_t)d * NT + q0 + t] = qs[t][d];
    }
}

// ---------------------------------------------------------------------------
extern "C" void kernel_launch(void* const* d_in, const int* in_sizes, int n_in,
                              void* d_out, int out_size)
{
    const float* x    = (const float*)d_in[0];
    const float* c    = (const float*)d_in[1];
    const float* q_w  = (const float*)d_in[2];
    const float* q_b  = (const float*)d_in[3];
    const float* kv_w = (const float*)d_in[4];
    const float* kv_b = (const float*)d_in[5];
    const float* o_w  = (const float*)d_in[6];
    const float* o_b  = (const float*)d_in[7];
    float* out = (float*)d_out;

    // q = q_w @ x + q_b            (M=1024, K=1024, N=1024, per batch)
    sgemm_bias_kernel<0><<<dim3(8, 8, NB), 256>>>(q_w, x, q_b, nullptr, NC, NC, NT);
    // kv = kv_w @ c + kv_b         (M=2048)
    sgemm_bias_kernel<1><<<dim3(8, 16, NB), 256>>>(kv_w, c, kv_b, nullptr, 2 * NC, NC, NT);
    // attention (RoPE fused)
    attn_kernel<<<dim3(NT / 64, NH, NB), 256>>>();
    // out = o_w @ g_att + o_b  (g_att read inside MODE==2 kernel)
    sgemm_bias_kernel<2><<<dim3(8, 8, NB), 256>>>(o_w, nullptr, o_b, out, NC, NC, NT);
}

// round 5
// speedup vs baseline: 1.5994x; 1.5994x over previous
#include <cuda_runtime.h>
#include <cuda_bf16.h>
#include <math_constants.h>
#include <cstdint>

#define NB 4
#define NC 1024
#define NT 1024
#define NH 16
#define NDH 64
#define KDIM 1024

// ---------------------------------------------------------------------------
// Scratch (__device__ globals; allocation-free)
// ---------------------------------------------------------------------------
__device__ float g_q[NB * NC * NT];        // 16 MB fp32
__device__ float g_kv[NB * 2 * NC * NT];   // 32 MB fp32
__device__ float g_att[NB * NC * NT];      // 16 MB fp32
// Split weights: [q(1M) | kv(2M) | o(1M)] elems
__device__ __align__(16) __nv_bfloat16 g_w_hi[4 * 1024 * 1024];
__device__ __align__(16) __nv_bfloat16 g_w_lo[4 * 1024 * 1024];
// Split + transposed activations [T][C]: [x(4M) | c(4M) | att(4M)] elems
__device__ __align__(16) __nv_bfloat16 g_a_hi[12 * 1024 * 1024];
__device__ __align__(16) __nv_bfloat16 g_a_lo[12 * 1024 * 1024];

// ---------------------------------------------------------------------------
// Base-ISA tensor helpers (sm_80+ features; compile for plain sm_100)
// ---------------------------------------------------------------------------
__device__ __forceinline__ uint32_t smem_to_u32(const void* p) {
    uint32_t a;
    asm("{ .reg .u64 t; cvta.to.shared.u64 t, %1; cvt.u32.u64 %0, t; }"
        : "=r"(a) : "l"(p));
    return a;
}
#define CP_ASYNC16(dst, src) \
    asm volatile("cp.async.cg.shared.global [%0], [%1], 16;" \
        :: "r"(dst), "l"(src) : "memory")
#define CP_COMMIT() asm volatile("cp.async.commit_group;" ::: "memory")
#define CP_WAIT(n)  asm volatile("cp.async.wait_group %0;" :: "n"(n) : "memory")
#define LDMX4(r, addr) \
    asm volatile("ldmatrix.sync.aligned.m8n8.x4.shared.b16 {%0,%1,%2,%3}, [%4];" \
        : "=r"((r)[0]), "=r"((r)[1]), "=r"((r)[2]), "=r"((r)[3]) : "r"(addr))
#define LDMX2(r, addr) \
    asm volatile("ldmatrix.sync.aligned.m8n8.x2.shared.b16 {%0,%1}, [%2];" \
        : "=r"((r)[0]), "=r"((r)[1]) : "r"(addr))

__device__ __forceinline__ void mma_bf16(float* c, const uint32_t* a,
                                         const uint32_t* b) {
    asm volatile(
        "mma.sync.aligned.m16n8k16.row.col.f32.bf16.bf16.f32 "
        "{%0,%1,%2,%3}, {%4,%5,%6,%7}, {%8,%9}, {%0,%1,%2,%3};"
        : "+f"(c[0]), "+f"(c[1]), "+f"(c[2]), "+f"(c[3])
        : "r"(a[0]), "r"(a[1]), "r"(a[2]), "r"(a[3]), "r"(b[0]), "r"(b[1]));
}

// ---------------------------------------------------------------------------
// Weight split: hi = bf16(w), lo = bf16(w - hi)
// ---------------------------------------------------------------------------
__global__ __launch_bounds__(256) void split_w_kernel(
    const float* __restrict__ src, size_t dst_off, int count)
{
    int stride = gridDim.x * blockDim.x;
    for (int i = blockIdx.x * blockDim.x + threadIdx.x; i < count; i += stride) {
        float v = src[i];
        __nv_bfloat16 h = __float2bfloat16(v);
        g_w_hi[dst_off + i] = h;
        g_w_lo[dst_off + i] = __float2bfloat16(v - __bfloat162float(h));
    }
}

// ---------------------------------------------------------------------------
// Activation transpose + split: src [C][T] fp32 -> dst [T][C] bf16 hi/lo
// SRCMODE 0: src = arg; 1: src = g_att
// ---------------------------------------------------------------------------
template <int SRCMODE>
__global__ __launch_bounds__(256) void tsplit_kernel(
    const float* __restrict__ srcArg, size_t dst_off)
{
    __shared__ float tile[32][33];
    const float* src =
        (SRCMODE == 1 ? (const float*)g_att : srcArg) + (size_t)blockIdx.z * NC * NT;
    const int t0 = blockIdx.x * 32, c0 = blockIdx.y * 32;
    const int tx = threadIdx.x, ty = threadIdx.y;
#pragma unroll
    for (int i = 0; i < 4; i++)
        tile[ty + 8 * i][tx] = src[(size_t)(c0 + ty + 8 * i) * NT + t0 + tx];
    __syncthreads();
    size_t db = dst_off + (size_t)blockIdx.z * NC * NT;
#pragma unroll
    for (int i = 0; i < 4; i++) {
        float v = tile[tx][ty + 8 * i];
        size_t o = db + (size_t)(t0 + ty + 8 * i) * NC + c0 + tx;
        __nv_bfloat16 h = __float2bfloat16(v);
        g_a_hi[o] = h;
        g_a_lo[o] = __float2bfloat16(v - __bfloat162float(h));
    }
}

// ---------------------------------------------------------------------------
// bf16-split GEMM via mma.sync: Y[m][n] = sum_k W[m][k] X[k][n] + bias[m]
// A = W rows (K-major), B = Xt rows (K-major, col-major operand).
// 128x128 CTA tile, 8 warps (2x4), warp tile 64x32, K-chunk 64 bf16,
// cp.async double buffer, SW128 XOR swizzle, ldmatrix fragments.
// YMODE 0: Y=g_q, 1: Y=g_kv, 2: Y=Yarg(d_out)
// ---------------------------------------------------------------------------
#define BUF_BYTES 65536u
#define OFF_A_HI 0u
#define OFF_A_LO 16384u
#define OFF_B_HI 32768u
#define OFF_B_LO 49152u
#define SMEM_MMA (2 * 65536)

template <int YMODE>
__global__ __launch_bounds__(256) void mma_gemm_kernel(
    size_t w_off, size_t a_off, const float* __restrict__ bias,
    float* __restrict__ Yarg, int M)
{
    extern __shared__ char sm[];
    const uint32_t smb = smem_to_u32(sm);
    const int tid = threadIdx.x;
    const int wid = tid >> 5, lane = tid & 31;
    const int b = blockIdx.z;
    const int m0 = blockIdx.y * 128, n0 = blockIdx.x * 128;
    const int wm = (wid >> 2) * 64;   // 0 or 64
    const int wn = (wid & 3) * 32;    // 0,32,64,96

    const __nv_bfloat16* Wh = g_w_hi + w_off;
    const __nv_bfloat16* Wl = g_w_lo + w_off;
    const __nv_bfloat16* Xh = g_a_hi + a_off + (size_t)b * (NC * NT);
    const __nv_bfloat16* Xl = g_a_lo + a_off + (size_t)b * (NC * NT);

    float acc[4][4][4];
#pragma unroll
    for (int mt = 0; mt < 4; mt++)
#pragma unroll
        for (int nt = 0; nt < 4; nt++)
#pragma unroll
            for (int i = 0; i < 4; i++) acc[mt][nt][i] = 0.f;

    // Staging: 4 arrays of [128 rows][64 bf16] = 16KB each, SW128 swizzle.
    auto stage = [&](int ch, int buf) {
        const uint32_t base = smb + buf * BUF_BYTES;
        const int k0 = ch * 64;
#pragma unroll
        for (int it = 0; it < 4; it++) {
            const int idx = tid + it * 256;
            const int row = idx >> 3, v = idx & 7;
            const uint32_t dst = base + row * 128 + ((v * 16) ^ ((row & 7) << 4));
            CP_ASYNC16(dst + OFF_A_HI, Wh + (size_t)(m0 + row) * KDIM + k0 + v * 8);
            CP_ASYNC16(dst + OFF_A_LO, Wl + (size_t)(m0 + row) * KDIM + k0 + v * 8);
            CP_ASYNC16(dst + OFF_B_HI, Xh + (size_t)(n0 + row) * KDIM + k0 + v * 8);
            CP_ASYNC16(dst + OFF_B_LO, Xl + (size_t)(n0 + row) * KDIM + k0 + v * 8);
        }
        CP_COMMIT();
    };

    stage(0, 0);

    // ldmatrix lane-address components
    const int a_row_in = (lane & 7) + ((lane >> 3) & 1) * 8;  // row within 16
    const int a_colsel = (lane >> 4) & 1;                     // k half (0/1)
    const int b_row_in = lane & 7;
    const int b_colsel = (lane >> 3) & 1;

    for (int ch = 0; ch < 16; ch++) {
        if (ch < 15) { stage(ch + 1, (ch + 1) & 1); CP_WAIT(1); }
        else         { CP_WAIT(0); }
        __syncthreads();
        const uint32_t base = smb + (ch & 1) * BUF_BYTES;

#pragma unroll
        for (int ks = 0; ks < 4; ks++) {
            uint32_t ah[4][4], al[4][4];
#pragma unroll
            for (int mt = 0; mt < 4; mt++) {
                const int r = wm + mt * 16 + a_row_in;
                const uint32_t col = (uint32_t)(ks * 32 + a_colsel * 16);
                const uint32_t addr = base + r * 128 + (col ^ ((r & 7) << 4));
                LDMX4(ah[mt], addr + OFF_A_HI);
                LDMX4(al[mt], addr + OFF_A_LO);
            }
            uint32_t bh[4][2], bl[4][2];
#pragma unroll
            for (int nt = 0; nt < 4; nt++) {
                const int r = wn + nt * 8 + b_row_in;
                const uint32_t col = (uint32_t)(ks * 32 + b_colsel * 16);
                const uint32_t addr = base + r * 128 + (col ^ ((r & 7) << 4));
                LDMX2(bh[nt], addr + OFF_B_HI);
                LDMX2(bl[nt], addr + OFF_B_LO);
            }
#pragma unroll
            for (int mt = 0; mt < 4; mt++)
#pragma unroll
                for (int nt = 0; nt < 4; nt++) {
                    mma_bf16(acc[mt][nt], ah[mt], bh[nt]);
                    mma_bf16(acc[mt][nt], ah[mt], bl[nt]);
                    mma_bf16(acc[mt][nt], al[mt], bh[nt]);
                }
        }
        __syncthreads();
    }

    // Epilogue: fragment rows/cols, float2 stores + bias
    float* Ybase;
    if (YMODE == 0)      Ybase = g_q;
    else if (YMODE == 1) Ybase = g_kv;
    else                 Ybase = Yarg;
    float* Yb = Ybase + (size_t)b * M * NT;

#pragma unroll
    for (int mt = 0; mt < 4; mt++) {
        const int r0 = m0 + wm + mt * 16 + (lane >> 2);
        const float bv0 = bias[r0], bv1 = bias[r0 + 8];
#pragma unroll
        for (int nt = 0; nt < 4; nt++) {
            const int cn = n0 + wn + nt * 8 + (lane & 3) * 2;
            *(float2*)&Yb[(size_t)r0 * NT + cn] =
                make_float2(acc[mt][nt][0] + bv0, acc[mt][nt][1] + bv0);
            *(float2*)&Yb[(size_t)(r0 + 8) * NT + cn] =
                make_float2(acc[mt][nt][2] + bv1, acc[mt][nt][3] + bv1);
        }
    }
}

// ---------------------------------------------------------------------------
// Fused RoPE + flash attention (unchanged from R3)
// ---------------------------------------------------------------------------
__global__ __launch_bounds__(256) void attn_kernel()
{
    __shared__ float qs[64][65];
    __shared__ float ks[32][65];
    __shared__ float vs[32][65];
    __shared__ float ps[64][33];
    __shared__ float s_m[64], s_l[64], s_alpha[64];

    const int tid = threadIdx.x;
    const int tx = tid & 15, ty = tid >> 4;
    const int b = blockIdx.z, h = blockIdx.y;
    const int q0 = blockIdx.x * 64;

    const float* qg = g_q + (size_t)b * NC * NT + (size_t)h * NDH * NT;
    const float* kg = g_kv + (size_t)b * 2 * NC * NT + (size_t)h * NDH * NT;
    const float* vg = kg + (size_t)NC * NT;

    const float LN1E4_16 = 0.57564627324851145f;  // ln(10000)/16

    for (int idx = tid; idx < 64 * 64; idx += 256) {
        int d = idx >> 6, t = idx & 63;
        qs[t][d] = qg[(size_t)d * NT + q0 + t];
    }
    if (tid < 64) { s_m[tid] = -CUDART_INF_F; s_l[tid] = 0.f; }
    __syncthreads();

    for (int idx = tid; idx < 64 * 16; idx += 256) {
        int t = idx >> 4, j = idx & 15;
        float theta = __expf(-(float)j * LN1E4_16);
        float ang = (float)(q0 + t) * theta;
        float sn, cs;
        sincosf(ang, &sn, &cs);
        float x0 = qs[t][j], x1 = qs[t][j + 16];
        qs[t][j]      = x0 * cs - x1 * sn;
        qs[t][j + 16] = x1 * cs + x0 * sn;
    }

    float O[4][4];
#pragma unroll
    for (int i = 0; i < 4; i++)
#pragma unroll
        for (int j = 0; j < 4; j++) O[i][j] = 0.f;

    __syncthreads();

    for (int k0 = 0; k0 < NT; k0 += 32) {
        for (int idx = tid; idx < 32 * 64; idx += 256) {
            int d = idx >> 5, t = idx & 31;
            ks[t][d] = kg[(size_t)d * NT + k0 + t];
            vs[t][d] = vg[(size_t)d * NT + k0 + t];
        }
        __syncthreads();
        for (int idx = tid; idx < 32 * 16; idx += 256) {
            int t = idx >> 4, j = idx & 15;
            float theta = __expf(-(float)j * LN1E4_16);
            float ang = (float)(k0 + t) * theta;
            float sn, cs;
            sincosf(ang, &sn, &cs);
            float x0 = ks[t][j], x1 = ks[t][j + 16];
            ks[t][j]      = x0 * cs - x1 * sn;
            ks[t][j + 16] = x1 * cs + x0 * sn;
        }
        __syncthreads();

        float sacc[4][2];
#pragma unroll
        for (int ii = 0; ii < 4; ii++) { sacc[ii][0] = 0.f; sacc[ii][1] = 0.f; }
#pragma unroll 16
        for (int d = 0; d < 64; d++) {
            float kv0 = ks[tx * 2][d];
            float kv1 = ks[tx * 2 + 1][d];
#pragma unroll
            for (int ii = 0; ii < 4; ii++) {
                float qv = qs[ty * 4 + ii][d];
                sacc[ii][0] = fmaf(qv, kv0, sacc[ii][0]);
                sacc[ii][1] = fmaf(qv, kv1, sacc[ii][1]);
            }
        }
#pragma unroll
        for (int ii = 0; ii < 4; ii++) {
            ps[ty * 4 + ii][tx * 2]     = sacc[ii][0] * 0.125f;
            ps[ty * 4 + ii][tx * 2 + 1] = sacc[ii][1] * 0.125f;
        }
        __syncthreads();

        if (tid < 64) {
            int r = tid;
            float mx = -CUDART_INF_F;
#pragma unroll 8
            for (int j = 0; j < 32; j++) mx = fmaxf(mx, ps[r][j]);
            float m_new = fmaxf(s_m[r], mx);
            float alpha = __expf(s_m[r] - m_new);
            float l = s_l[r] * alpha;
#pragma unroll 8
            for (int j = 0; j < 32; j++) {
                float p = __expf(ps[r][j] - m_new);
                ps[r][j] = p;
                l += p;
            }
            s_m[r] = m_new;
            s_l[r] = l;
            s_alpha[r] = alpha;
        }
        __syncthreads();

#pragma unroll
        for (int ii = 0; ii < 4; ii++) {
            float a = s_alpha[ty * 4 + ii];
#pragma unroll
            for (int dd = 0; dd < 4; dd++) O[ii][dd] *= a;
        }
#pragma unroll 8
        for (int j = 0; j < 32; j++) {
            float v0 = vs[j][tx * 4];
            float v1 = vs[j][tx * 4 + 1];
            float v2 = vs[j][tx * 4 + 2];
            float v3 = vs[j][tx * 4 + 3];
#pragma unroll
            for (int ii = 0; ii < 4; ii++) {
                float p = ps[ty * 4 + ii][j];
                O[ii][0] = fmaf(p, v0, O[ii][0]);
                O[ii][1] = fmaf(p, v1, O[ii][1]);
                O[ii][2] = fmaf(p, v2, O[ii][2]);
                O[ii][3] = fmaf(p, v3, O[ii][3]);
            }
        }
        __syncthreads();
    }

#pragma unroll
    for (int ii = 0; ii < 4; ii++) {
        float inv_l = 1.f / s_l[ty * 4 + ii];
#pragma unroll
        for (int dd = 0; dd < 4; dd++)
            qs[ty * 4 + ii][tx * 4 + dd] = O[ii][dd] * inv_l;
    }
    __syncthreads();
    float* og = g_att + (size_t)b * NC * NT + (size_t)h * NDH * NT;
    for (int idx = tid; idx < 64 * 64; idx += 256) {
        int d = idx >> 6, t = idx & 63;
        og[(size_t)d * NT + q0 + t] = qs[t][d];
    }
}

// ---------------------------------------------------------------------------
extern "C" void kernel_launch(void* const* d_in, const int* in_sizes, int n_in,
                              void* d_out, int out_size)
{
    const float* x    = (const float*)d_in[0];
    const float* c    = (const float*)d_in[1];
    const float* q_w  = (const float*)d_in[2];
    const float* q_b  = (const float*)d_in[3];
    const float* kv_w = (const float*)d_in[4];
    const float* kv_b = (const float*)d_in[5];
    const float* o_w  = (const float*)d_in[6];
    const float* o_b  = (const float*)d_in[7];
    float* out = (float*)d_out;

    static bool attr_done = false;
    if (!attr_done) {
        cudaFuncSetAttribute(mma_gemm_kernel<0>, cudaFuncAttributeMaxDynamicSharedMemorySize, SMEM_MMA);
        cudaFuncSetAttribute(mma_gemm_kernel<1>, cudaFuncAttributeMaxDynamicSharedMemorySize, SMEM_MMA);
        cudaFuncSetAttribute(mma_gemm_kernel<2>, cudaFuncAttributeMaxDynamicSharedMemorySize, SMEM_MMA);
        attr_done = true;
    }

    // Split weights (q | kv | o)
    split_w_kernel<<<1024, 256>>>(q_w, 0, 1024 * 1024);
    split_w_kernel<<<1024, 256>>>(kv_w, 1024 * 1024, 2 * 1024 * 1024);
    split_w_kernel<<<1024, 256>>>(o_w, 3 * 1024 * 1024, 1024 * 1024);
    // Transpose + split activations x, c
    tsplit_kernel<0><<<dim3(32, 32, NB), dim3(32, 8)>>>(x, 0);
    tsplit_kernel<0><<<dim3(32, 32, NB), dim3(32, 8)>>>(c, (size_t)4 * 1024 * 1024);
    // q = q_w @ x + q_b
    mma_gemm_kernel<0><<<dim3(8, 8, NB), 256, SMEM_MMA>>>(
        0, 0, q_b, nullptr, NC);
    // kv = kv_w @ c + kv_b
    mma_gemm_kernel<1><<<dim3(8, 16, NB), 256, SMEM_MMA>>>(
        (size_t)1024 * 1024, (size_t)4 * 1024 * 1024, kv_b, nullptr, 2 * NC);
    // attention (RoPE fused)
    attn_kernel<<<dim3(NT / 64, NH, NB), 256>>>();
    // transpose + split attention output
    tsplit_kernel<1><<<dim3(32, 32, NB), dim3(32, 8)>>>(nullptr, (size_t)8 * 1024 * 1024);
    // out = o_w @ att + o_b
    mma_gemm_kernel<2><<<dim3(8, 8, NB), 256, SMEM_MMA>>>(
        (size_t)3 * 1024 * 1024, (size_t)8 * 1024 * 1024, o_b, out, NC);
}

// round 6
// speedup vs baseline: 1.7913x; 1.1200x over previous
#include <cuda_runtime.h>
#include <cuda_bf16.h>
#include <math_constants.h>
#include <cstdint>

#define NB 4
#define NC 1024
#define NT 1024
#define NH 16
#define NDH 64
#define KDIM 1024

// ---------------------------------------------------------------------------
// Scratch (__device__ globals; allocation-free)
// ---------------------------------------------------------------------------
__device__ float g_q[NB * NC * NT];        // fp32 q (c-major)
__device__ float g_kv[NB * 2 * NC * NT];   // fp32 kv (c-major)
// Split weights: [q(1M) | kv(2M) | o(1M)] elems
__device__ __align__(16) __nv_bfloat16 g_w_hi[4 * 1024 * 1024];
__device__ __align__(16) __nv_bfloat16 g_w_lo[4 * 1024 * 1024];
// Split + transposed activations [T][C]: [x(4M) | c(4M) | att(4M)] elems
__device__ __align__(16) __nv_bfloat16 g_a_hi[12 * 1024 * 1024];
__device__ __align__(16) __nv_bfloat16 g_a_lo[12 * 1024 * 1024];
// RoPE'd q/k/v split, [b][h][t][64] rows: [q(4M) | k(4M) | v(4M)]
__device__ __align__(16) __nv_bfloat16 g_qkvh[12 * 1024 * 1024];
__device__ __align__(16) __nv_bfloat16 g_qkvl[12 * 1024 * 1024];

#define QOFF ((size_t)0)
#define KOFF ((size_t)4 * 1024 * 1024)
#define VOFF ((size_t)8 * 1024 * 1024)
#define ATTOFF ((size_t)8 * 1024 * 1024)   // att region inside g_a_hi/lo

// ---------------------------------------------------------------------------
// Base-ISA tensor helpers (sm_80+ features; compile for plain sm_100)
// ---------------------------------------------------------------------------
__device__ __forceinline__ uint32_t smem_to_u32(const void* p) {
    uint32_t a;
    asm("{ .reg .u64 t; cvta.to.shared.u64 t, %1; cvt.u32.u64 %0, t; }"
        : "=r"(a) : "l"(p));
    return a;
}
#define CP_ASYNC16(dst, src) \
    asm volatile("cp.async.cg.shared.global [%0], [%1], 16;" \
        :: "r"(dst), "l"(src) : "memory")
#define CP_COMMIT() asm volatile("cp.async.commit_group;" ::: "memory")
#define CP_WAIT(n)  asm volatile("cp.async.wait_group %0;" :: "n"(n) : "memory")
#define LDMX4(r, addr) \
    asm volatile("ldmatrix.sync.aligned.m8n8.x4.shared.b16 {%0,%1,%2,%3}, [%4];" \
        : "=r"((r)[0]), "=r"((r)[1]), "=r"((r)[2]), "=r"((r)[3]) : "r"(addr))
#define LDMX2(r, addr) \
    asm volatile("ldmatrix.sync.aligned.m8n8.x2.shared.b16 {%0,%1}, [%2];" \
        : "=r"((r)[0]), "=r"((r)[1]) : "r"(addr))
#define LDMX2T(r, addr) \
    asm volatile("ldmatrix.sync.aligned.m8n8.x2.trans.shared.b16 {%0,%1}, [%2];" \
        : "=r"((r)[0]), "=r"((r)[1]) : "r"(addr))

__device__ __forceinline__ void mma_bf16(float* c, const uint32_t* a,
                                         const uint32_t* b) {
    asm volatile(
        "mma.sync.aligned.m16n8k16.row.col.f32.bf16.bf16.f32 "
        "{%0,%1,%2,%3}, {%4,%5,%6,%7}, {%8,%9}, {%0,%1,%2,%3};"
        : "+f"(c[0]), "+f"(c[1]), "+f"(c[2]), "+f"(c[3])
        : "r"(a[0]), "r"(a[1]), "r"(a[2]), "r"(a[3]), "r"(b[0]), "r"(b[1]));
}

// ---------------------------------------------------------------------------
// Weight split: hi = bf16(w), lo = bf16(w - hi)
// ---------------------------------------------------------------------------
__global__ __launch_bounds__(256) void split_w_kernel(
    const float* __restrict__ src, size_t dst_off, int count)
{
    int stride = gridDim.x * blockDim.x;
    for (int i = blockIdx.x * blockDim.x + threadIdx.x; i < count; i += stride) {
        float v = src[i];
        __nv_bfloat16 h = __float2bfloat16(v);
        g_w_hi[dst_off + i] = h;
        g_w_lo[dst_off + i] = __float2bfloat16(v - __bfloat162float(h));
    }
}

// ---------------------------------------------------------------------------
// Activation transpose + split: src [C][T] fp32 -> dst [T][C] bf16 hi/lo
// ---------------------------------------------------------------------------
__global__ __launch_bounds__(256) void tsplit_kernel(
    const float* __restrict__ srcArg, size_t dst_off)
{
    __shared__ float tile[32][33];
    const float* src = srcArg + (size_t)blockIdx.z * NC * NT;
    const int t0 = blockIdx.x * 32, c0 = blockIdx.y * 32;
    const int tx = threadIdx.x, ty = threadIdx.y;
#pragma unroll
    for (int i = 0; i < 4; i++)
        tile[ty + 8 * i][tx] = src[(size_t)(c0 + ty + 8 * i) * NT + t0 + tx];
    __syncthreads();
    size_t db = dst_off + (size_t)blockIdx.z * NC * NT;
#pragma unroll
    for (int i = 0; i < 4; i++) {
        float v = tile[tx][ty + 8 * i];
        size_t o = db + (size_t)(t0 + ty + 8 * i) * NC + c0 + tx;
        __nv_bfloat16 h = __float2bfloat16(v);
        g_a_hi[o] = h;
        g_a_lo[o] = __float2bfloat16(v - __bfloat162float(h));
    }
}

// ---------------------------------------------------------------------------
// q/k/v prep: read fp32 projections (c-major), apply RoPE (q,k; first 32 d),
// split to bf16 hi/lo, write [b][h][t][64] rows.
// SRC 0: q (rope), 1: k (rope), 2: v (no rope)
// Grid: (NT/32, 2, NB*NH). Block (32, 8). c0 = blockIdx.y*32 within head.
// ---------------------------------------------------------------------------
template <int SRC>
__global__ __launch_bounds__(256) void qkv_prep_kernel()
{
    __shared__ float tile[32][33];
    const int z = blockIdx.z;           // b*NH + h
    const int b = z >> 4, h = z & 15;
    const int t0 = blockIdx.x * 32, c0 = blockIdx.y * 32;
    const int tx = threadIdx.x, ty = threadIdx.y;

    const float* src;
    if (SRC == 0)      src = g_q  + (size_t)b * NC * NT + (size_t)(h * 64) * NT;
    else if (SRC == 1) src = g_kv + (size_t)b * 2 * NC * NT + (size_t)(h * 64) * NT;
    else               src = g_kv + (size_t)b * 2 * NC * NT + (size_t)(NC + h * 64) * NT;

#pragma unroll
    for (int i = 0; i < 4; i++)
        tile[ty + 8 * i][tx] = src[(size_t)(c0 + ty + 8 * i) * NT + t0 + tx];
    __syncthreads();

    const size_t roff = (SRC == 0 ? QOFF : (SRC == 1 ? KOFF : VOFF));
    const float LN1E4_16 = 0.57564627324851145f;  // ln(10000)/16

#pragma unroll
    for (int i = 0; i < 4; i++) {
        const int t = t0 + ty + 8 * i;
        float val;
        if (SRC < 2 && c0 == 0) {
            const int j = tx & 15;
            float theta = __expf(-(float)j * LN1E4_16);
            float sn, cs;
            sincosf((float)t * theta, &sn, &cs);
            float x0 = tile[tx][ty + 8 * i];
            if (tx < 16) {
                float x1 = tile[tx + 16][ty + 8 * i];
                val = x0 * cs - x1 * sn;
            } else {
                float xm = tile[tx - 16][ty + 8 * i];
                val = x0 * cs + xm * sn;
            }
        } else {
            val = tile[tx][ty + 8 * i];
        }
        size_t o = roff + ((size_t)z * NT + t) * 64 + c0 + tx;
        __nv_bfloat16 hh = __float2bfloat16(val);
        g_qkvh[o] = hh;
        g_qkvl[o] = __float2bfloat16(val - __bfloat162float(hh));
    }
}

// ---------------------------------------------------------------------------
// bf16-split GEMM via mma.sync (unchanged from R5)
// ---------------------------------------------------------------------------
#define BUF_BYTES 65536u
#define OFF_A_HI 0u
#define OFF_A_LO 16384u
#define OFF_B_HI 32768u
#define OFF_B_LO 49152u
#define SMEM_MMA (2 * 65536)

template <int YMODE>
__global__ __launch_bounds__(256) void mma_gemm_kernel(
    size_t w_off, size_t a_off, const float* __restrict__ bias,
    float* __restrict__ Yarg, int M)
{
    extern __shared__ char sm[];
    const uint32_t smb = smem_to_u32(sm);
    const int tid = threadIdx.x;
    const int wid = tid >> 5, lane = tid & 31;
    const int b = blockIdx.z;
    const int m0 = blockIdx.y * 128, n0 = blockIdx.x * 128;
    const int wm = (wid >> 2) * 64;
    const int wn = (wid & 3) * 32;

    const __nv_bfloat16* Wh = g_w_hi + w_off;
    const __nv_bfloat16* Wl = g_w_lo + w_off;
    const __nv_bfloat16* Xh = g_a_hi + a_off + (size_t)b * (NC * NT);
    const __nv_bfloat16* Xl = g_a_lo + a_off + (size_t)b * (NC * NT);

    float acc[4][4][4];
#pragma unroll
    for (int mt = 0; mt < 4; mt++)
#pragma unroll
        for (int nt = 0; nt < 4; nt++)
#pragma unroll
            for (int i = 0; i < 4; i++) acc[mt][nt][i] = 0.f;

    auto stage = [&](int ch, int buf) {
        const uint32_t base = smb + buf * BUF_BYTES;
        const int k0 = ch * 64;
#pragma unroll
        for (int it = 0; it < 4; it++) {
            const int idx = tid + it * 256;
            const int row = idx >> 3, v = idx & 7;
            const uint32_t dst = base + row * 128 + ((v * 16) ^ ((row & 7) << 4));
            CP_ASYNC16(dst + OFF_A_HI, Wh + (size_t)(m0 + row) * KDIM + k0 + v * 8);
            CP_ASYNC16(dst + OFF_A_LO, Wl + (size_t)(m0 + row) * KDIM + k0 + v * 8);
            CP_ASYNC16(dst + OFF_B_HI, Xh + (size_t)(n0 + row) * KDIM + k0 + v * 8);
            CP_ASYNC16(dst + OFF_B_LO, Xl + (size_t)(n0 + row) * KDIM + k0 + v * 8);
        }
        CP_COMMIT();
    };

    stage(0, 0);

    const int a_row_in = (lane & 7) + ((lane >> 3) & 1) * 8;
    const int a_colsel = (lane >> 4) & 1;
    const int b_row_in = lane & 7;
    const int b_colsel = (lane >> 3) & 1;

    for (int ch = 0; ch < 16; ch++) {
        if (ch < 15) { stage(ch + 1, (ch + 1) & 1); CP_WAIT(1); }
        else         { CP_WAIT(0); }
        __syncthreads();
        const uint32_t base = smb + (ch & 1) * BUF_BYTES;

#pragma unroll
        for (int ks = 0; ks < 4; ks++) {
            uint32_t ah[4][4], al[4][4];
#pragma unroll
            for (int mt = 0; mt < 4; mt++) {
                const int r = wm + mt * 16 + a_row_in;
                const uint32_t col = (uint32_t)(ks * 32 + a_colsel * 16);
                const uint32_t addr = base + r * 128 + (col ^ ((r & 7) << 4));
                LDMX4(ah[mt], addr + OFF_A_HI);
                LDMX4(al[mt], addr + OFF_A_LO);
            }
            uint32_t bh[4][2], bl[4][2];
#pragma unroll
            for (int nt = 0; nt < 4; nt++) {
                const int r = wn + nt * 8 + b_row_in;
                const uint32_t col = (uint32_t)(ks * 32 + b_colsel * 16);
                const uint32_t addr = base + r * 128 + (col ^ ((r & 7) << 4));
                LDMX2(bh[nt], addr + OFF_B_HI);
                LDMX2(bl[nt], addr + OFF_B_LO);
            }
#pragma unroll
            for (int mt = 0; mt < 4; mt++)
#pragma unroll
                for (int nt = 0; nt < 4; nt++) {
                    mma_bf16(acc[mt][nt], ah[mt], bh[nt]);
                    mma_bf16(acc[mt][nt], ah[mt], bl[nt]);
                    mma_bf16(acc[mt][nt], al[mt], bh[nt]);
                }
        }
        __syncthreads();
    }

    float* Ybase;
    if (YMODE == 0)      Ybase = g_q;
    else if (YMODE == 1) Ybase = g_kv;
    else                 Ybase = Yarg;
    float* Yb = Ybase + (size_t)b * M * NT;

#pragma unroll
    for (int mt = 0; mt < 4; mt++) {
        const int r0 = m0 + wm + mt * 16 + (lane >> 2);
        const float bv0 = bias[r0], bv1 = bias[r0 + 8];
#pragma unroll
        for (int nt = 0; nt < 4; nt++) {
            const int cn = n0 + wn + nt * 8 + (lane & 3) * 2;
            *(float2*)&Yb[(size_t)r0 * NT + cn] =
                make_float2(acc[mt][nt][0] + bv0, acc[mt][nt][1] + bv0);
            *(float2*)&Yb[(size_t)(r0 + 8) * NT + cn] =
                make_float2(acc[mt][nt][2] + bv1, acc[mt][nt][3] + bv1);
        }
    }
}

// ---------------------------------------------------------------------------
// Tensor-core flash attention with bf16-split mma.sync.
// Grid (T/128, NH, NB), 256 threads (8 warps), 1 CTA/SM.
// Key chunks of 64. S warp tile 64x16 (2x4 warps); PV warp tile 64x16 d.
// ---------------------------------------------------------------------------
#define A_QH 0u
#define A_QL 16384u
#define A_KH 32768u
#define A_KL 40960u
#define A_VH 49152u
#define A_VL 57344u
#define A_PS 65536u          // fp32 [128][68]
#define A_PBH 100352u        // bf16 [128][72]
#define A_PBL 118784u
#define A_SM 137216u
#define A_SL 137728u
#define A_SA 138240u
#define SMEM_ATT 138752

__global__ __launch_bounds__(256) void attn_mma_kernel()
{
    extern __shared__ char sm[];
    const uint32_t smb = smem_to_u32(sm);
    const int tid = threadIdx.x, wid = tid >> 5, lane = tid & 31;
    const int b = blockIdx.z, h = blockIdx.y;
    const int q0 = blockIdx.x * 128;
    const int z = b * NH + h;

    float* ps  = (float*)(sm + A_PS);
    float* s_m = (float*)(sm + A_SM);
    float* s_l = (float*)(sm + A_SL);
    float* s_a = (float*)(sm + A_SA);

    // Load Q tile (hi/lo), SW128-swizzled
    {
        const __nv_bfloat16* qh = g_qkvh + QOFF + ((size_t)z * NT + q0) * 64;
        const __nv_bfloat16* ql = g_qkvl + QOFF + ((size_t)z * NT + q0) * 64;
        for (int idx = tid; idx < 1024; idx += 256) {
            const int row = idx >> 3, v = idx & 7;
            const uint32_t d = row * 128 + ((v * 16) ^ ((row & 7) << 4));
            *(uint4*)(sm + A_QH + d) = *((const uint4*)(qh + row * 64) + v);
            *(uint4*)(sm + A_QL + d) = *((const uint4*)(ql + row * 64) + v);
        }
    }
    if (tid < 128) { s_m[tid] = -CUDART_INF_F; s_l[tid] = 0.f; }

    float oacc[4][2][4];
#pragma unroll
    for (int mt = 0; mt < 4; mt++)
#pragma unroll
        for (int nt = 0; nt < 2; nt++)
#pragma unroll
            for (int i = 0; i < 4; i++) oacc[mt][nt][i] = 0.f;

    const int a_row = (lane & 7) + ((lane >> 3) & 1) * 8;
    const int a_cs  = (lane >> 4) & 1;
    const int b_row = lane & 7;
    const int b_cs  = (lane >> 3) & 1;
    const int wm = (wid >> 2) * 64;   // m rows: 0/64
    const int wn = (wid & 3) * 16;    // S key cols / PV d cols

    const __nv_bfloat16* kh_g = g_qkvh + KOFF + (size_t)z * NT * 64;
    const __nv_bfloat16* kl_g = g_qkvl + KOFF + (size_t)z * NT * 64;
    const __nv_bfloat16* vh_g = g_qkvh + VOFF + (size_t)z * NT * 64;
    const __nv_bfloat16* vl_g = g_qkvl + VOFF + (size_t)z * NT * 64;

    for (int ch = 0; ch < 16; ch++) {
        __syncthreads();  // Q/s_m ready (first) | ps/pb/KV free (rest)
        const int k0 = ch * 64;
        for (int idx = tid; idx < 512; idx += 256) {
            const int row = idx >> 3, v = idx & 7;
            const uint32_t d = row * 128 + ((v * 16) ^ ((row & 7) << 4));
            const size_t go = (size_t)(k0 + row) * 64;
            *(uint4*)(sm + A_KH + d) = *((const uint4*)(kh_g + go) + v);
            *(uint4*)(sm + A_KL + d) = *((const uint4*)(kl_g + go) + v);
            *(uint4*)(sm + A_VH + d) = *((const uint4*)(vh_g + go) + v);
            *(uint4*)(sm + A_VL + d) = *((const uint4*)(vl_g + go) + v);
        }
        __syncthreads();

        // ---- S = Q K^T (split), warp tile 64x16 ----
        float sacc[4][2][4];
#pragma unroll
        for (int mt = 0; mt < 4; mt++)
#pragma unroll
            for (int nt = 0; nt < 2; nt++)
#pragma unroll
                for (int i = 0; i < 4; i++) sacc[mt][nt][i] = 0.f;

#pragma unroll
        for (int ks = 0; ks < 4; ks++) {
            uint32_t ah[4][4], al[4][4];
#pragma unroll
            for (int mt = 0; mt < 4; mt++) {
                const int r = wm + mt * 16 + a_row;
                const uint32_t col = (uint32_t)(ks * 32 + a_cs * 16);
                const uint32_t ad = smb + r * 128 + (col ^ ((r & 7) << 4));
                LDMX4(ah[mt], ad + A_QH);
                LDMX4(al[mt], ad + A_QL);
            }
            uint32_t bh[2][2], bl[2][2];
#pragma unroll
            for (int nt = 0; nt < 2; nt++) {
                const int r = wn + nt * 8 + b_row;
                const uint32_t col = (uint32_t)(ks * 32 + b_cs * 16);
                const uint32_t ad = smb + r * 128 + (col ^ ((r & 7) << 4));
                LDMX2(bh[nt], ad + A_KH);
                LDMX2(bl[nt], ad + A_KL);
            }
#pragma unroll
            for (int mt = 0; mt < 4; mt++)
#pragma unroll
                for (int nt = 0; nt < 2; nt++) {
                    mma_bf16(sacc[mt][nt], ah[mt], bh[nt]);
                    mma_bf16(sacc[mt][nt], ah[mt], bl[nt]);
                    mma_bf16(sacc[mt][nt], al[mt], bh[nt]);
                }
        }
        // store scaled S to ps
#pragma unroll
        for (int mt = 0; mt < 4; mt++) {
            const int r = wm + mt * 16 + (lane >> 2);
#pragma unroll
            for (int nt = 0; nt < 2; nt++) {
                const int cn = wn + nt * 8 + (lane & 3) * 2;
                ps[r * 68 + cn]           = sacc[mt][nt][0] * 0.125f;
                ps[r * 68 + cn + 1]       = sacc[mt][nt][1] * 0.125f;
                ps[(r + 8) * 68 + cn]     = sacc[mt][nt][2] * 0.125f;
                ps[(r + 8) * 68 + cn + 1] = sacc[mt][nt][3] * 0.125f;
            }
        }
        __syncthreads();

        // ---- online softmax, one thread per row ----
        if (tid < 128) {
            const int r = tid;
            float mx = -CUDART_INF_F;
#pragma unroll
            for (int j = 0; j < 16; j++) {
                float4 v4 = *(float4*)&ps[r * 68 + j * 4];
                mx = fmaxf(mx, fmaxf(fmaxf(v4.x, v4.y), fmaxf(v4.z, v4.w)));
            }
            const float mo = s_m[r];
            const float mn = fmaxf(mo, mx);
            const float alpha = __expf(mo - mn);
            float l = s_l[r] * alpha;
            __nv_bfloat16* pbh = (__nv_bfloat16*)(sm + A_PBH) + r * 72;
            __nv_bfloat16* pbl = (__nv_bfloat16*)(sm + A_PBL) + r * 72;
#pragma unroll 8
            for (int j = 0; j < 64; j++) {
                const float p = __expf(ps[r * 68 + j] - mn);
                l += p;
                const __nv_bfloat16 hh = __float2bfloat16(p);
                pbh[j] = hh;
                pbl[j] = __float2bfloat16(p - __bfloat162float(hh));
            }
            s_m[r] = mn; s_l[r] = l; s_a[r] = alpha;
        }
        __syncthreads();

        // ---- O = O*alpha + P V (split) ----
#pragma unroll
        for (int mt = 0; mt < 4; mt++) {
            const int r1 = wm + mt * 16 + (lane >> 2);
            const float a1 = s_a[r1], a2 = s_a[r1 + 8];
#pragma unroll
            for (int nt = 0; nt < 2; nt++) {
                oacc[mt][nt][0] *= a1; oacc[mt][nt][1] *= a1;
                oacc[mt][nt][2] *= a2; oacc[mt][nt][3] *= a2;
            }
        }
#pragma unroll
        for (int ks = 0; ks < 4; ks++) {
            uint32_t ph[4][4], pl[4][4];
#pragma unroll
            for (int mt = 0; mt < 4; mt++) {
                const int r = wm + mt * 16 + a_row;
                const uint32_t ad = smb + A_PBH + r * 144 + ks * 32 + a_cs * 16;
                LDMX4(ph[mt], ad);
                LDMX4(pl[mt], ad + (A_PBL - A_PBH));
            }
            uint32_t vhf[2][2], vlf[2][2];
#pragma unroll
            for (int nt = 0; nt < 2; nt++) {
                const int k = ks * 16 + (lane & 15);
                const uint32_t col = (uint32_t)((wn + nt * 8) * 2);
                const uint32_t ad = smb + k * 128 + (col ^ ((k & 7) << 4));
                LDMX2T(vhf[nt], ad + A_VH);
                LDMX2T(vlf[nt], ad + A_VL);
            }
#pragma unroll
            for (int mt = 0; mt < 4; mt++)
#pragma unroll
                for (int nt = 0; nt < 2; nt++) {
                    mma_bf16(oacc[mt][nt], ph[mt], vhf[nt]);
                    mma_bf16(oacc[mt][nt], ph[mt], vlf[nt]);
                    mma_bf16(oacc[mt][nt], pl[mt], vhf[nt]);
                }
        }
    }

    // ---- epilogue: normalize, stage, write split bf16 to att region ----
    __syncthreads();
#pragma unroll
    for (int mt = 0; mt < 4; mt++) {
        const int r1 = wm + mt * 16 + (lane >> 2);
        const float il1 = 1.f / s_l[r1], il2 = 1.f / s_l[r1 + 8];
#pragma unroll
        for (int nt = 0; nt < 2; nt++) {
            const int cn = wn + nt * 8 + (lane & 3) * 2;
            ps[r1 * 68 + cn]           = oacc[mt][nt][0] * il1;
            ps[r1 * 68 + cn + 1]       = oacc[mt][nt][1] * il1;
            ps[(r1 + 8) * 68 + cn]     = oacc[mt][nt][2] * il2;
            ps[(r1 + 8) * 68 + cn + 1] = oacc[mt][nt][3] * il2;
        }
    }
    __syncthreads();
    for (int idx = tid; idx < 128 * 64; idx += 256) {
        const int t = idx >> 6, d = idx & 63;
        const float v = ps[t * 68 + d];
        const size_t o = ATTOFF + (size_t)b * (NC * NT) +
                         (size_t)(q0 + t) * NC + h * 64 + d;
        const __nv_bfloat16 hh = __float2bfloat16(v);
        g_a_hi[o] = hh;
        g_a_lo[o] = __float2bfloat16(v - __bfloat162float(hh));
    }
}

// ---------------------------------------------------------------------------
extern "C" void kernel_launch(void* const* d_in, const int* in_sizes, int n_in,
                              void* d_out, int out_size)
{
    const float* x    = (const float*)d_in[0];
    const float* c    = (const float*)d_in[1];
    const float* q_w  = (const float*)d_in[2];
    const float* q_b  = (const float*)d_in[3];
    const float* kv_w = (const float*)d_in[4];
    const float* kv_b = (const float*)d_in[5];
    const float* o_w  = (const float*)d_in[6];
    const float* o_b  = (const float*)d_in[7];
    float* out = (float*)d_out;

    static bool attr_done = false;
    if (!attr_done) {
        cudaFuncSetAttribute(mma_gemm_kernel<0>, cudaFuncAttributeMaxDynamicSharedMemorySize, SMEM_MMA);
        cudaFuncSetAttribute(mma_gemm_kernel<1>, cudaFuncAttributeMaxDynamicSharedMemorySize, SMEM_MMA);
        cudaFuncSetAttribute(mma_gemm_kernel<2>, cudaFuncAttributeMaxDynamicSharedMemorySize, SMEM_MMA);
        cudaFuncSetAttribute(attn_mma_kernel, cudaFuncAttributeMaxDynamicSharedMemorySize, SMEM_ATT);
        attr_done = true;
    }

    // Split weights (q | kv | o)
    split_w_kernel<<<1024, 256>>>(q_w, 0, 1024 * 1024);
    split_w_kernel<<<1024, 256>>>(kv_w, 1024 * 1024, 2 * 1024 * 1024);
    split_w_kernel<<<1024, 256>>>(o_w, 3 * 1024 * 1024, 1024 * 1024);
    // Transpose + split activations x, c
    tsplit_kernel<<<dim3(32, 32, NB), dim3(32, 8)>>>(x, 0);
    tsplit_kernel<<<dim3(32, 32, NB), dim3(32, 8)>>>(c, (size_t)4 * 1024 * 1024);
    // q = q_w @ x + q_b ; kv = kv_w @ c + kv_b
    mma_gemm_kernel<0><<<dim3(8, 8, NB), 256, SMEM_MMA>>>(0, 0, q_b, nullptr, NC);
    mma_gemm_kernel<1><<<dim3(8, 16, NB), 256, SMEM_MMA>>>(
        (size_t)1024 * 1024, (size_t)4 * 1024 * 1024, kv_b, nullptr, 2 * NC);
    // RoPE + split q/k/v
    qkv_prep_kernel<0><<<dim3(32, 2, NB * NH), dim3(32, 8)>>>();
    qkv_prep_kernel<1><<<dim3(32, 2, NB * NH), dim3(32, 8)>>>();
    qkv_prep_kernel<2><<<dim3(32, 2, NB * NH), dim3(32, 8)>>>();
    // tensor-core flash attention (writes split bf16 att activations)
    attn_mma_kernel<<<dim3(NT / 128, NH, NB), 256, SMEM_ATT>>>();
    // out = o_w @ att + o_b
    mma_gemm_kernel<2><<<dim3(8, 8, NB), 256, SMEM_MMA>>>(
        (size_t)3 * 1024 * 1024, (size_t)8 * 1024 * 1024, o_b, out, NC);
}

// round 8
// speedup vs baseline: 2.9248x; 1.6327x over previous
#include <cuda_runtime.h>
#include <cuda_bf16.h>
#include <math_constants.h>
#include <cstdint>

#define NB 4
#define NC 1024
#define NT 1024
#define NH 16
#define NDH 64
#define KDIM 1024

// ---------------------------------------------------------------------------
// Scratch (__device__ globals; allocation-free)
// ---------------------------------------------------------------------------
__device__ float g_q[NB * NC * NT];        // fp32 q (c-major)
__device__ float g_kv[NB * 2 * NC * NT];   // fp32 kv (c-major)
// Split weights: [q(1M) | kv(2M) | o(1M)] elems
__device__ __align__(16) __nv_bfloat16 g_w_hi[4 * 1024 * 1024];
__device__ __align__(16) __nv_bfloat16 g_w_lo[4 * 1024 * 1024];
// Split + transposed activations [T][C]: [x(4M) | c(4M) | att(4M)] elems
__device__ __align__(16) __nv_bfloat16 g_a_hi[12 * 1024 * 1024];
__device__ __align__(16) __nv_bfloat16 g_a_lo[12 * 1024 * 1024];
// RoPE'd q/k/v split, [b][h][t][64] rows: [q(4M) | k(4M) | v(4M)]
__device__ __align__(16) __nv_bfloat16 g_qkvh[12 * 1024 * 1024];
__device__ __align__(16) __nv_bfloat16 g_qkvl[12 * 1024 * 1024];

#define QOFF ((size_t)0)
#define KOFF ((size_t)4 * 1024 * 1024)
#define VOFF ((size_t)8 * 1024 * 1024)
#define ATTOFF ((size_t)8 * 1024 * 1024)   // att region inside g_a_hi/lo

// ---------------------------------------------------------------------------
// Base-ISA tensor helpers (sm_80+ features; compile for plain sm_100)
// ---------------------------------------------------------------------------
__device__ __forceinline__ uint32_t smem_to_u32(const void* p) {
    uint32_t a;
    asm("{ .reg .u64 t; cvta.to.shared.u64 t, %1; cvt.u32.u64 %0, t; }"
        : "=r"(a) : "l"(p));
    return a;
}
#define CP_ASYNC16(dst, src) \
    asm volatile("cp.async.cg.shared.global [%0], [%1], 16;" \
        :: "r"(dst), "l"(src) : "memory")
#define CP_COMMIT() asm volatile("cp.async.commit_group;" ::: "memory")
#define CP_WAIT(n)  asm volatile("cp.async.wait_group %0;" :: "n"(n) : "memory")
#define LDMX4(r, addr) \
    asm volatile("ldmatrix.sync.aligned.m8n8.x4.shared.b16 {%0,%1,%2,%3}, [%4];" \
        : "=r"((r)[0]), "=r"((r)[1]), "=r"((r)[2]), "=r"((r)[3]) : "r"(addr))
#define LDMX2(r, addr) \
    asm volatile("ldmatrix.sync.aligned.m8n8.x2.shared.b16 {%0,%1}, [%2];" \
        : "=r"((r)[0]), "=r"((r)[1]) : "r"(addr))
#define LDMX2T(r, addr) \
    asm volatile("ldmatrix.sync.aligned.m8n8.x2.trans.shared.b16 {%0,%1}, [%2];" \
        : "=r"((r)[0]), "=r"((r)[1]) : "r"(addr))

__device__ __forceinline__ void mma_bf16(float* c, const uint32_t* a,
                                         const uint32_t* b) {
    asm volatile(
        "mma.sync.aligned.m16n8k16.row.col.f32.bf16.bf16.f32 "
        "{%0,%1,%2,%3}, {%4,%5,%6,%7}, {%8,%9}, {%0,%1,%2,%3};"
        : "+f"(c[0]), "+f"(c[1]), "+f"(c[2]), "+f"(c[3])
        : "r"(a[0]), "r"(a[1]), "r"(a[2]), "r"(a[3]), "r"(b[0]), "r"(b[1]));
}

// Split two floats into bf16 hi-pair and lo-pair (packed b16x2)
__device__ __forceinline__ void split2(float a, float b, uint32_t& hp, uint32_t& lp) {
    __nv_bfloat16 ha = __float2bfloat16(a), hb = __float2bfloat16(b);
    __nv_bfloat162 hh = __nv_bfloat162(ha, hb);
    __nv_bfloat162 ll = __nv_bfloat162(
        __float2bfloat16(a - __bfloat162float(ha)),
        __float2bfloat16(b - __bfloat162float(hb)));
    hp = *(uint32_t*)&hh;
    lp = *(uint32_t*)&ll;
}

// ---------------------------------------------------------------------------
// Weight split: hi = bf16(w), lo = bf16(w - hi)
// ---------------------------------------------------------------------------
__global__ __launch_bounds__(256) void split_w_kernel(
    const float* __restrict__ src, size_t dst_off, int count)
{
    int stride = gridDim.x * blockDim.x;
    for (int i = blockIdx.x * blockDim.x + threadIdx.x; i < count; i += stride) {
        float v = src[i];
        __nv_bfloat16 h = __float2bfloat16(v);
        g_w_hi[dst_off + i] = h;
        g_w_lo[dst_off + i] = __float2bfloat16(v - __bfloat162float(h));
    }
}

// ---------------------------------------------------------------------------
// Activation transpose + split: src [C][T] fp32 -> dst [T][C] bf16 hi/lo
// ---------------------------------------------------------------------------
__global__ __launch_bounds__(256) void tsplit_kernel(
    const float* __restrict__ srcArg, size_t dst_off)
{
    __shared__ float tile[32][33];
    const float* src = srcArg + (size_t)blockIdx.z * NC * NT;
    const int t0 = blockIdx.x * 32, c0 = blockIdx.y * 32;
    const int tx = threadIdx.x, ty = threadIdx.y;
#pragma unroll
    for (int i = 0; i < 4; i++)
        tile[ty + 8 * i][tx] = src[(size_t)(c0 + ty + 8 * i) * NT + t0 + tx];
    __syncthreads();
    size_t db = dst_off + (size_t)blockIdx.z * NC * NT;
#pragma unroll
    for (int i = 0; i < 4; i++) {
        float v = tile[tx][ty + 8 * i];
        size_t o = db + (size_t)(t0 + ty + 8 * i) * NC + c0 + tx;
        __nv_bfloat16 h = __float2bfloat16(v);
        g_a_hi[o] = h;
        g_a_lo[o] = __float2bfloat16(v - __bfloat162float(h));
    }
}

// ---------------------------------------------------------------------------
// q/k/v prep: RoPE + split, [b][h][t][64] rows.
// ---------------------------------------------------------------------------
template <int SRC>
__global__ __launch_bounds__(256) void qkv_prep_kernel()
{
    __shared__ float tile[32][33];
    const int z = blockIdx.z;
    const int b = z >> 4, h = z & 15;
    const int t0 = blockIdx.x * 32, c0 = blockIdx.y * 32;
    const int tx = threadIdx.x, ty = threadIdx.y;

    const float* src;
    if (SRC == 0)      src = g_q  + (size_t)b * NC * NT + (size_t)(h * 64) * NT;
    else if (SRC == 1) src = g_kv + (size_t)b * 2 * NC * NT + (size_t)(h * 64) * NT;
    else               src = g_kv + (size_t)b * 2 * NC * NT + (size_t)(NC + h * 64) * NT;

#pragma unroll
    for (int i = 0; i < 4; i++)
        tile[ty + 8 * i][tx] = src[(size_t)(c0 + ty + 8 * i) * NT + t0 + tx];
    __syncthreads();

    const size_t roff = (SRC == 0 ? QOFF : (SRC == 1 ? KOFF : VOFF));
    const float LN1E4_16 = 0.57564627324851145f;

#pragma unroll
    for (int i = 0; i < 4; i++) {
        const int t = t0 + ty + 8 * i;
        float val;
        if (SRC < 2 && c0 == 0) {
            const int j = tx & 15;
            float theta = __expf(-(float)j * LN1E4_16);
            float sn, cs;
            sincosf((float)t * theta, &sn, &cs);
            float x0 = tile[tx][ty + 8 * i];
            if (tx < 16) {
                float x1 = tile[tx + 16][ty + 8 * i];
                val = x0 * cs - x1 * sn;
            } else {
                float xm = tile[tx - 16][ty + 8 * i];
                val = x0 * cs + xm * sn;
            }
        } else {
            val = tile[tx][ty + 8 * i];
        }
        size_t o = roff + ((size_t)z * NT + t) * 64 + c0 + tx;
        __nv_bfloat16 hh = __float2bfloat16(val);
        g_qkvh[o] = hh;
        g_qkvl[o] = __float2bfloat16(val - __bfloat162float(hh));
    }
}

// ---------------------------------------------------------------------------
// bf16-split GEMM via mma.sync
// ---------------------------------------------------------------------------
#define BUF_BYTES 65536u
#define OFF_A_HI 0u
#define OFF_A_LO 16384u
#define OFF_B_HI 32768u
#define OFF_B_LO 49152u
#define SMEM_MMA (2 * 65536)

template <int YMODE>
__global__ __launch_bounds__(256) void mma_gemm_kernel(
    size_t w_off, size_t a_off, const float* __restrict__ bias,
    float* __restrict__ Yarg, int M)
{
    extern __shared__ char sm[];
    const uint32_t smb = smem_to_u32(sm);
    const int tid = threadIdx.x;
    const int wid = tid >> 5, lane = tid & 31;
    const int b = blockIdx.z;
    const int m0 = blockIdx.y * 128, n0 = blockIdx.x * 128;
    const int wm = (wid >> 2) * 64;
    const int wn = (wid & 3) * 32;

    const __nv_bfloat16* Wh = g_w_hi + w_off;
    const __nv_bfloat16* Wl = g_w_lo + w_off;
    const __nv_bfloat16* Xh = g_a_hi + a_off + (size_t)b * (NC * NT);
    const __nv_bfloat16* Xl = g_a_lo + a_off + (size_t)b * (NC * NT);

    float acc[4][4][4];
#pragma unroll
    for (int mt = 0; mt < 4; mt++)
#pragma unroll
        for (int nt = 0; nt < 4; nt++)
#pragma unroll
            for (int i = 0; i < 4; i++) acc[mt][nt][i] = 0.f;

    auto stage = [&](int ch, int buf) {
        const uint32_t base = smb + buf * BUF_BYTES;
        const int k0 = ch * 64;
#pragma unroll
        for (int it = 0; it < 4; it++) {
            const int idx = tid + it * 256;
            const int row = idx >> 3, v = idx & 7;
            const uint32_t dst = base + row * 128 + ((v * 16) ^ ((row & 7) << 4));
            CP_ASYNC16(dst + OFF_A_HI, Wh + (size_t)(m0 + row) * KDIM + k0 + v * 8);
            CP_ASYNC16(dst + OFF_A_LO, Wl + (size_t)(m0 + row) * KDIM + k0 + v * 8);
            CP_ASYNC16(dst + OFF_B_HI, Xh + (size_t)(n0 + row) * KDIM + k0 + v * 8);
            CP_ASYNC16(dst + OFF_B_LO, Xl + (size_t)(n0 + row) * KDIM + k0 + v * 8);
        }
        CP_COMMIT();
    };

    stage(0, 0);

    const int a_row_in = (lane & 7) + ((lane >> 3) & 1) * 8;
    const int a_colsel = (lane >> 4) & 1;
    const int b_row_in = lane & 7;
    const int b_colsel = (lane >> 3) & 1;

    for (int ch = 0; ch < 16; ch++) {
        if (ch < 15) { stage(ch + 1, (ch + 1) & 1); CP_WAIT(1); }
        else         { CP_WAIT(0); }
        __syncthreads();
        const uint32_t base = smb + (ch & 1) * BUF_BYTES;

#pragma unroll
        for (int ks = 0; ks < 4; ks++) {
            uint32_t ah[4][4], al[4][4];
#pragma unroll
            for (int mt = 0; mt < 4; mt++) {
                const int r = wm + mt * 16 + a_row_in;
                const uint32_t col = (uint32_t)(ks * 32 + a_colsel * 16);
                const uint32_t addr = base + r * 128 + (col ^ ((r & 7) << 4));
                LDMX4(ah[mt], addr + OFF_A_HI);
                LDMX4(al[mt], addr + OFF_A_LO);
            }
            uint32_t bh[4][2], bl[4][2];
#pragma unroll
            for (int nt = 0; nt < 4; nt++) {
                const int r = wn + nt * 8 + b_row_in;
                const uint32_t col = (uint32_t)(ks * 32 + b_colsel * 16);
                const uint32_t addr = base + r * 128 + (col ^ ((r & 7) << 4));
                LDMX2(bh[nt], addr + OFF_B_HI);
                LDMX2(bl[nt], addr + OFF_B_LO);
            }
#pragma unroll
            for (int mt = 0; mt < 4; mt++)
#pragma unroll
                for (int nt = 0; nt < 4; nt++) {
                    mma_bf16(acc[mt][nt], ah[mt], bh[nt]);
                    mma_bf16(acc[mt][nt], ah[mt], bl[nt]);
                    mma_bf16(acc[mt][nt], al[mt], bh[nt]);
                }
        }
        __syncthreads();
    }

    float* Ybase;
    if (YMODE == 0)      Ybase = g_q;
    else if (YMODE == 1) Ybase = g_kv;
    else                 Ybase = Yarg;
    float* Yb = Ybase + (size_t)b * M * NT;

#pragma unroll
    for (int mt = 0; mt < 4; mt++) {
        const int r0 = m0 + wm + mt * 16 + (lane >> 2);
        const float bv0 = bias[r0], bv1 = bias[r0 + 8];
#pragma unroll
        for (int nt = 0; nt < 4; nt++) {
            const int cn = n0 + wn + nt * 8 + (lane & 3) * 2;
            *(float2*)&Yb[(size_t)r0 * NT + cn] =
                make_float2(acc[mt][nt][0] + bv0, acc[mt][nt][1] + bv0);
            *(float2*)&Yb[(size_t)(r0 + 8) * NT + cn] =
                make_float2(acc[mt][nt][2] + bv1, acc[mt][nt][3] + bv1);
        }
    }
}

// ---------------------------------------------------------------------------
// Register-resident FA2 attention, bf16-split mma.sync.
// Grid (T/128, NH, NB), 256 threads (8 warps). Each warp owns 16 query rows
// x ALL 64 keys per chunk -> softmax entirely in registers (quad shuffles).
// Q frags loaded once; K/V cp.async double-buffered; P packed to bf16 frags
// in registers (C-frag layout == A-frag layout identity).
// ---------------------------------------------------------------------------
#define KV_BUF 32768u
#define SMEM_ATT (2 * 32768)

__global__ __launch_bounds__(256) void attn_mma_kernel()
{
    extern __shared__ char sm[];
    const uint32_t smb = smem_to_u32(sm);
    const int tid = threadIdx.x, wid = tid >> 5, lane = tid & 31;
    const int b = blockIdx.z, h = blockIdx.y;
    const int q0 = blockIdx.x * 128;
    const int z = b * NH + h;
    const int wm = wid * 16;

    // ---- stage Q (hi 16KB | lo 16KB) into smem, load frags, free smem ----
    {
        const __nv_bfloat16* qhp = g_qkvh + QOFF + ((size_t)z * NT + q0) * 64;
        const __nv_bfloat16* qlp = g_qkvl + QOFF + ((size_t)z * NT + q0) * 64;
        for (int idx = tid; idx < 1024; idx += 256) {
            const int row = idx >> 3, v = idx & 7;
            const uint32_t d = row * 128 + ((v * 16) ^ ((row & 7) << 4));
            *(uint4*)(sm + d)          = *((const uint4*)(qhp + row * 64) + v);
            *(uint4*)(sm + 16384 + d)  = *((const uint4*)(qlp + row * 64) + v);
        }
    }
    __syncthreads();

    const int a_row = (lane & 7) + ((lane >> 3) & 1) * 8;
    const int a_cs  = (lane >> 4) & 1;
    uint32_t qh[4][4], ql[4][4];
#pragma unroll
    for (int ks = 0; ks < 4; ks++) {
        const int r = wm + a_row;
        const uint32_t addr =
            smb + r * 128 + ((uint32_t)(ks * 32 + a_cs * 16) ^ ((r & 7) << 4));
        LDMX4(qh[ks], addr);
        LDMX4(ql[ks], addr + 16384);
    }
    __syncthreads();   // all warps done reading Q staging

    // ---- KV staging ----
    const __nv_bfloat16* kh_g = g_qkvh + KOFF + (size_t)z * NT * 64;
    const __nv_bfloat16* kl_g = g_qkvl + KOFF + (size_t)z * NT * 64;
    const __nv_bfloat16* vh_g = g_qkvh + VOFF + (size_t)z * NT * 64;
    const __nv_bfloat16* vl_g = g_qkvl + VOFF + (size_t)z * NT * 64;

    auto stageKV = [&](int ch, int buf) {
        const uint32_t base = smb + buf * KV_BUF;
        const int k0 = ch * 64;
#pragma unroll
        for (int it = 0; it < 2; it++) {
            const int idx = tid + it * 256;       // 0..511
            const int row = idx >> 3, v = idx & 7;
            const uint32_t d = row * 128 + ((v * 16) ^ ((row & 7) << 4));
            const size_t go = (size_t)(k0 + row) * 64 + v * 8;
            CP_ASYNC16(base + d,         kh_g + go);
            CP_ASYNC16(base + 8192 + d,  kl_g + go);
            CP_ASYNC16(base + 16384 + d, vh_g + go);
            CP_ASYNC16(base + 24576 + d, vl_g + go);
        }
        CP_COMMIT();
    };
    stageKV(0, 0);

    float m0 = -CUDART_INF_F, m1 = -CUDART_INF_F;
    float l0 = 0.f, l1 = 0.f;
    float oacc[8][4];
#pragma unroll
    for (int nt = 0; nt < 8; nt++)
#pragma unroll
        for (int i = 0; i < 4; i++) oacc[nt][i] = 0.f;

    const int b_row = lane & 7;
    const int b_cs  = (lane >> 3) & 1;

    for (int ch = 0; ch < 16; ch++) {
        if (ch < 15) { stageKV(ch + 1, (ch + 1) & 1); CP_WAIT(1); }
        else         { CP_WAIT(0); }
        __syncthreads();
        const uint32_t base = smb + (ch & 1) * KV_BUF;

        // ---- S = Q K^T (split): warp tile 16 rows x 64 keys ----
        float sacc[8][4];
#pragma unroll
        for (int nt = 0; nt < 8; nt++)
#pragma unroll
            for (int i = 0; i < 4; i++) sacc[nt][i] = 0.f;

#pragma unroll
        for (int ks = 0; ks < 4; ks++) {
#pragma unroll
            for (int nt = 0; nt < 8; nt++) {
                uint32_t bh[2], bl[2];
                const int r = nt * 8 + b_row;
                const uint32_t addr =
                    base + r * 128 + ((uint32_t)(ks * 32 + b_cs * 16) ^ ((r & 7) << 4));
                LDMX2(bh, addr);
                LDMX2(bl, addr + 8192);
                mma_bf16(sacc[nt], qh[ks], bh);
                mma_bf16(sacc[nt], qh[ks], bl);
                mma_bf16(sacc[nt], ql[ks], bh);
            }
        }

        // ---- in-register online softmax (rows r = wm+lane/4, r+8) ----
        float mx0 = -CUDART_INF_F, mx1 = -CUDART_INF_F;
#pragma unroll
        for (int nt = 0; nt < 8; nt++) {
            sacc[nt][0] *= 0.125f; sacc[nt][1] *= 0.125f;
            sacc[nt][2] *= 0.125f; sacc[nt][3] *= 0.125f;
            mx0 = fmaxf(mx0, fmaxf(sacc[nt][0], sacc[nt][1]));
            mx1 = fmaxf(mx1, fmaxf(sacc[nt][2], sacc[nt][3]));
        }
        mx0 = fmaxf(mx0, __shfl_xor_sync(0xffffffffu, mx0, 1));
        mx0 = fmaxf(mx0, __shfl_xor_sync(0xffffffffu, mx0, 2));
        mx1 = fmaxf(mx1, __shfl_xor_sync(0xffffffffu, mx1, 1));
        mx1 = fmaxf(mx1, __shfl_xor_sync(0xffffffffu, mx1, 2));
        const float mn0 = fmaxf(m0, mx0), mn1 = fmaxf(m1, mx1);
        const float al0 = __expf(m0 - mn0), al1 = __expf(m1 - mn1);
        m0 = mn0; m1 = mn1;
        float ls0 = 0.f, ls1 = 0.f;
#pragma unroll
        for (int nt = 0; nt < 8; nt++) {
            sacc[nt][0] = __expf(sacc[nt][0] - mn0);
            sacc[nt][1] = __expf(sacc[nt][1] - mn0);
            sacc[nt][2] = __expf(sacc[nt][2] - mn1);
            sacc[nt][3] = __expf(sacc[nt][3] - mn1);
            ls0 += sacc[nt][0] + sacc[nt][1];
            ls1 += sacc[nt][2] + sacc[nt][3];
        }
        ls0 += __shfl_xor_sync(0xffffffffu, ls0, 1);
        ls0 += __shfl_xor_sync(0xffffffffu, ls0, 2);
        ls1 += __shfl_xor_sync(0xffffffffu, ls1, 1);
        ls1 += __shfl_xor_sync(0xffffffffu, ls1, 2);
        l0 = l0 * al0 + ls0;
        l1 = l1 * al1 + ls1;
#pragma unroll
        for (int nt = 0; nt < 8; nt++) {
            oacc[nt][0] *= al0; oacc[nt][1] *= al0;
            oacc[nt][2] *= al1; oacc[nt][3] *= al1;
        }

        // ---- O += P V (split); P packed from sacc in registers ----
#pragma unroll
        for (int ksp = 0; ksp < 4; ksp++) {
            uint32_t ph[4], pl[4];
            split2(sacc[2 * ksp][0],     sacc[2 * ksp][1],     ph[0], pl[0]);
            split2(sacc[2 * ksp][2],     sacc[2 * ksp][3],     ph[1], pl[1]);
            split2(sacc[2 * ksp + 1][0], sacc[2 * ksp + 1][1], ph[2], pl[2]);
            split2(sacc[2 * ksp + 1][2], sacc[2 * ksp + 1][3], ph[3], pl[3]);
            const int k = ksp * 16 + (lane & 15);
#pragma unroll
            for (int nt = 0; nt < 8; nt++) {
                uint32_t vh[2], vl[2];
                const uint32_t addr =
                    base + 16384 + k * 128 + ((uint32_t)(nt * 16) ^ ((k & 7) << 4));
                LDMX2T(vh, addr);
                LDMX2T(vl, addr + 8192);
                mma_bf16(oacc[nt], ph, vh);
                mma_bf16(oacc[nt], ph, vl);
                mma_bf16(oacc[nt], pl, vh);
            }
        }
        __syncthreads();   // compute done before next stage overwrites
    }

    // ---- epilogue: normalize, write split bf16 to att region ----
    const float il0 = 1.f / l0, il1 = 1.f / l1;
    const int r = wm + (lane >> 2);
    const size_t rowo = ATTOFF + (size_t)b * (NC * NT) +
                        (size_t)(q0 + r) * NC + h * 64;
#pragma unroll
    for (int nt = 0; nt < 8; nt++) {
        const int d = nt * 8 + (lane & 3) * 2;
        const float v0 = oacc[nt][0] * il0, v1 = oacc[nt][1] * il0;
        const float v2 = oacc[nt][2] * il1, v3 = oacc[nt][3] * il1;
        __nv_bfloat16 h0 = __float2bfloat16(v0), h1 = __float2bfloat16(v1);
        __nv_bfloat16 h2 = __float2bfloat16(v2), h3 = __float2bfloat16(v3);
        *(__nv_bfloat162*)(g_a_hi + rowo + d) = __nv_bfloat162(h0, h1);
        *(__nv_bfloat162*)(g_a_lo + rowo + d) = __nv_bfloat162(
            __float2bfloat16(v0 - __bfloat162float(h0)),
            __float2bfloat16(v1 - __bfloat162float(h1)));
        *(__nv_bfloat162*)(g_a_hi + rowo + 8 * NC + d) = __nv_bfloat162(h2, h3);
        *(__nv_bfloat162*)(g_a_lo + rowo + 8 * NC + d) = __nv_bfloat162(
            __float2bfloat16(v2 - __bfloat162float(h2)),
            __float2bfloat16(v3 - __bfloat162float(h3)));
    }
}

// ---------------------------------------------------------------------------
extern "C" void kernel_launch(void* const* d_in, const int* in_sizes, int n_in,
                              void* d_out, int out_size)
{
    const float* x    = (const float*)d_in[0];
    const float* c    = (const float*)d_in[1];
    const float* q_w  = (const float*)d_in[2];
    const float* q_b  = (const float*)d_in[3];
    const float* kv_w = (const float*)d_in[4];
    const float* kv_b = (const float*)d_in[5];
    const float* o_w  = (const float*)d_in[6];
    const float* o_b  = (const float*)d_in[7];
    float* out = (float*)d_out;

    static bool attr_done = false;
    if (!attr_done) {
        cudaFuncSetAttribute(mma_gemm_kernel<0>, cudaFuncAttributeMaxDynamicSharedMemorySize, SMEM_MMA);
        cudaFuncSetAttribute(mma_gemm_kernel<1>, cudaFuncAttributeMaxDynamicSharedMemorySize, SMEM_MMA);
        cudaFuncSetAttribute(mma_gemm_kernel<2>, cudaFuncAttributeMaxDynamicSharedMemorySize, SMEM_MMA);
        cudaFuncSetAttribute(attn_mma_kernel, cudaFuncAttributeMaxDynamicSharedMemorySize, SMEM_ATT);
        attr_done = true;
    }

    // Split weights (q | kv | o)
    split_w_kernel<<<1024, 256>>>(q_w, 0, 1024 * 1024);
    split_w_kernel<<<1024, 256>>>(kv_w, 1024 * 1024, 2 * 1024 * 1024);
    split_w_kernel<<<1024, 256>>>(o_w, 3 * 1024 * 1024, 1024 * 1024);
    // Transpose + split activations x, c
    tsplit_kernel<<<dim3(32, 32, NB), dim3(32, 8)>>>(x, 0);
    tsplit_kernel<<<dim3(32, 32, NB), dim3(32, 8)>>>(c, (size_t)4 * 1024 * 1024);
    // q = q_w @ x + q_b ; kv = kv_w @ c + kv_b
    mma_gemm_kernel<0><<<dim3(8, 8, NB), 256, SMEM_MMA>>>(0, 0, q_b, nullptr, NC);
    mma_gemm_kernel<1><<<dim3(8, 16, NB), 256, SMEM_MMA>>>(
        (size_t)1024 * 1024, (size_t)4 * 1024 * 1024, kv_b, nullptr, 2 * NC);
    // RoPE + split q/k/v
    qkv_prep_kernel<0><<<dim3(32, 2, NB * NH), dim3(32, 8)>>>();
    qkv_prep_kernel<1><<<dim3(32, 2, NB * NH), dim3(32, 8)>>>();
    qkv_prep_kernel<2><<<dim3(32, 2, NB * NH), dim3(32, 8)>>>();
    // register-resident FA2 attention (writes split bf16 att activations)
    attn_mma_kernel<<<dim3(NT / 128, NH, NB), 256, SMEM_ATT>>>();
    // out = o_w @ att + o_b
    mma_gemm_kernel<2><<<dim3(8, 8, NB), 256, SMEM_MMA>>>(
        (size_t)3 * 1024 * 1024, (size_t)8 * 1024 * 1024, o_b, out, NC);
}

// round 9
// speedup vs baseline: 3.9233x; 1.3414x over previous
#include <cuda_runtime.h>
#include <cuda_fp16.h>
#include <math_constants.h>
#include <cstdint>

#define NB 4
#define NC 1024
#define NT 1024
#define NH 16
#define NDH 64
#define KDIM 1024

// ---------------------------------------------------------------------------
// Scratch (__device__ globals; allocation-free)
// ---------------------------------------------------------------------------
__device__ float g_q[NB * NC * NT];        // fp32 q (c-major)
__device__ float g_kv[NB * 2 * NC * NT];   // fp32 kv (c-major)
// Split weights (exact 2-term): [q(1M) | kv(2M) | o(1M)] elems
__device__ __align__(16) __half g_w_hi[4 * 1024 * 1024];
__device__ __align__(16) __half g_w_lo[4 * 1024 * 1024];
// Activations hi-only, [T][C] rows: [x(4M) | c(4M) | att(4M)] elems
__device__ __align__(16) __half g_a_h[12 * 1024 * 1024];
// RoPE'd q/k/v hi, [b][h][t][64] rows: [q(4M) | k(4M) | v(4M)]; q lo separate
__device__ __align__(16) __half g_qkvh[12 * 1024 * 1024];
__device__ __align__(16) __half g_qlo[4 * 1024 * 1024];

#define QOFF ((size_t)0)
#define KOFF ((size_t)4 * 1024 * 1024)
#define VOFF ((size_t)8 * 1024 * 1024)
#define XOFF ((size_t)0)
#define COFF ((size_t)4 * 1024 * 1024)
#define ATTOFF ((size_t)8 * 1024 * 1024)

// ---------------------------------------------------------------------------
// Base-ISA tensor helpers (sm_80+ features; compile for plain sm_100)
// ---------------------------------------------------------------------------
__device__ __forceinline__ uint32_t smem_to_u32(const void* p) {
    uint32_t a;
    asm("{ .reg .u64 t; cvta.to.shared.u64 t, %1; cvt.u32.u64 %0, t; }"
        : "=r"(a) : "l"(p));
    return a;
}
#define CP_ASYNC16(dst, src) \
    asm volatile("cp.async.cg.shared.global [%0], [%1], 16;" \
        :: "r"(dst), "l"(src) : "memory")
#define CP_COMMIT() asm volatile("cp.async.commit_group;" ::: "memory")
#define CP_WAIT(n)  asm volatile("cp.async.wait_group %0;" :: "n"(n) : "memory")
#define LDMX4(r, addr) \
    asm volatile("ldmatrix.sync.aligned.m8n8.x4.shared.b16 {%0,%1,%2,%3}, [%4];" \
        : "=r"((r)[0]), "=r"((r)[1]), "=r"((r)[2]), "=r"((r)[3]) : "r"(addr))
#define LDMX2(r, addr) \
    asm volatile("ldmatrix.sync.aligned.m8n8.x2.shared.b16 {%0,%1}, [%2];" \
        : "=r"((r)[0]), "=r"((r)[1]) : "r"(addr))
#define LDMX2T(r, addr) \
    asm volatile("ldmatrix.sync.aligned.m8n8.x2.trans.shared.b16 {%0,%1}, [%2];" \
        : "=r"((r)[0]), "=r"((r)[1]) : "r"(addr))

__device__ __forceinline__ void mma_f16(float* c, const uint32_t* a,
                                        const uint32_t* b) {
    asm volatile(
        "mma.sync.aligned.m16n8k16.row.col.f32.f16.f16.f32 "
        "{%0,%1,%2,%3}, {%4,%5,%6,%7}, {%8,%9}, {%0,%1,%2,%3};"
        : "+f"(c[0]), "+f"(c[1]), "+f"(c[2]), "+f"(c[3])
        : "r"(a[0]), "r"(a[1]), "r"(a[2]), "r"(a[3]), "r"(b[0]), "r"(b[1]));
}

// Split two floats into fp16 hi-pair and lo-pair (packed b16x2)
__device__ __forceinline__ void split2h(float a, float b, uint32_t& hp, uint32_t& lp) {
    __half ha = __float2half(a), hb = __float2half(b);
    __half2 hh = __halves2half2(ha, hb);
    __half2 ll = __halves2half2(__float2half(a - __half2float(ha)),
                                __float2half(b - __half2float(hb)));
    hp = *(uint32_t*)&hh;
    lp = *(uint32_t*)&ll;
}

// ---------------------------------------------------------------------------
// Weight split: hi = fp16(w), lo = fp16(w - hi)
// ---------------------------------------------------------------------------
__global__ __launch_bounds__(256) void split_w_kernel(
    const float* __restrict__ src, size_t dst_off, int count)
{
    int stride = gridDim.x * blockDim.x;
    for (int i = blockIdx.x * blockDim.x + threadIdx.x; i < count; i += stride) {
        float v = src[i];
        __half h = __float2half(v);
        g_w_hi[dst_off + i] = h;
        g_w_lo[dst_off + i] = __float2half(v - __half2float(h));
    }
}

// ---------------------------------------------------------------------------
// Activation transpose: src [C][T] fp32 -> dst [T][C] fp16 hi
// ---------------------------------------------------------------------------
__global__ __launch_bounds__(256) void tsplit_kernel(
    const float* __restrict__ srcArg, size_t dst_off)
{
    __shared__ float tile[32][33];
    const float* src = srcArg + (size_t)blockIdx.z * NC * NT;
    const int t0 = blockIdx.x * 32, c0 = blockIdx.y * 32;
    const int tx = threadIdx.x, ty = threadIdx.y;
#pragma unroll
    for (int i = 0; i < 4; i++)
        tile[ty + 8 * i][tx] = src[(size_t)(c0 + ty + 8 * i) * NT + t0 + tx];
    __syncthreads();
    size_t db = dst_off + (size_t)blockIdx.z * NC * NT;
#pragma unroll
    for (int i = 0; i < 4; i++)
        g_a_h[db + (size_t)(t0 + ty + 8 * i) * NC + c0 + tx] =
            __float2half(tile[tx][ty + 8 * i]);
}

// ---------------------------------------------------------------------------
// q/k/v prep: RoPE + fp16, [b][h][t][64] rows. q also writes lo.
// ---------------------------------------------------------------------------
template <int SRC>
__global__ __launch_bounds__(256) void qkv_prep_kernel()
{
    __shared__ float tile[32][33];
    const int z = blockIdx.z;
    const int b = z >> 4, h = z & 15;
    const int t0 = blockIdx.x * 32, c0 = blockIdx.y * 32;
    const int tx = threadIdx.x, ty = threadIdx.y;

    const float* src;
    if (SRC == 0)      src = g_q  + (size_t)b * NC * NT + (size_t)(h * 64) * NT;
    else if (SRC == 1) src = g_kv + (size_t)b * 2 * NC * NT + (size_t)(h * 64) * NT;
    else               src = g_kv + (size_t)b * 2 * NC * NT + (size_t)(NC + h * 64) * NT;

#pragma unroll
    for (int i = 0; i < 4; i++)
        tile[ty + 8 * i][tx] = src[(size_t)(c0 + ty + 8 * i) * NT + t0 + tx];
    __syncthreads();

    const size_t roff = (SRC == 0 ? QOFF : (SRC == 1 ? KOFF : VOFF));
    const float LN1E4_16 = 0.57564627324851145f;

#pragma unroll
    for (int i = 0; i < 4; i++) {
        const int t = t0 + ty + 8 * i;
        float val;
        if (SRC < 2 && c0 == 0) {
            const int j = tx & 15;
            float theta = __expf(-(float)j * LN1E4_16);
            float sn, cs;
            sincosf((float)t * theta, &sn, &cs);
            float x0 = tile[tx][ty + 8 * i];
            if (tx < 16) {
                float x1 = tile[tx + 16][ty + 8 * i];
                val = x0 * cs - x1 * sn;
            } else {
                float xm = tile[tx - 16][ty + 8 * i];
                val = x0 * cs + xm * sn;
            }
        } else {
            val = tile[tx][ty + 8 * i];
        }
        size_t o = ((size_t)z * NT + t) * 64 + c0 + tx;
        __half hh = __float2half(val);
        g_qkvh[roff + o] = hh;
        if (SRC == 0)
            g_qlo[o] = __float2half(val - __half2float(hh));
    }
}

// ---------------------------------------------------------------------------
// fp16 2-term GEMM tile body: Y[m][n] = sum_k W[m][k] X[k][n] + bias[m]
// D = Wh*Xh + Wl*Xh (X hi-only). 128x128 CTA tile, 8 warps, K-chunk 64,
// cp.async double buffer, 3 staged arrays (A_HI|A_LO|B_HI, 16KB each).
// ---------------------------------------------------------------------------
#define BUF_BYTES 49152u
#define OFF_A_HI 0u
#define OFF_A_LO 16384u
#define OFF_B_HI 32768u
#define SMEM_MMA (2 * 49152)

__device__ __forceinline__ void gemm_tile_body(
    const __half* __restrict__ Wh, const __half* __restrict__ Wl,
    const __half* __restrict__ Xh, const float* __restrict__ bias,
    float* __restrict__ Yb, int m0, int n0, char* sm)
{
    const uint32_t smb = smem_to_u32(sm);
    const int tid = threadIdx.x;
    const int wid = tid >> 5, lane = tid & 31;
    const int wm = (wid >> 2) * 64;
    const int wn = (wid & 3) * 32;

    float acc[4][4][4];
#pragma unroll
    for (int mt = 0; mt < 4; mt++)
#pragma unroll
        for (int nt = 0; nt < 4; nt++)
#pragma unroll
            for (int i = 0; i < 4; i++) acc[mt][nt][i] = 0.f;

    auto stage = [&](int ch, int buf) {
        const uint32_t base = smb + buf * BUF_BYTES;
        const int k0 = ch * 64;
#pragma unroll
        for (int it = 0; it < 4; it++) {
            const int idx = tid + it * 256;
            const int row = idx >> 3, v = idx & 7;
            const uint32_t dst = base + row * 128 + ((v * 16) ^ ((row & 7) << 4));
            CP_ASYNC16(dst + OFF_A_HI, Wh + (size_t)(m0 + row) * KDIM + k0 + v * 8);
            CP_ASYNC16(dst + OFF_A_LO, Wl + (size_t)(m0 + row) * KDIM + k0 + v * 8);
            CP_ASYNC16(dst + OFF_B_HI, Xh + (size_t)(n0 + row) * KDIM + k0 + v * 8);
        }
        CP_COMMIT();
    };

    stage(0, 0);

    const int a_row_in = (lane & 7) + ((lane >> 3) & 1) * 8;
    const int a_colsel = (lane >> 4) & 1;
    const int b_row_in = lane & 7;
    const int b_colsel = (lane >> 3) & 1;

    for (int ch = 0; ch < 16; ch++) {
        if (ch < 15) { stage(ch + 1, (ch + 1) & 1); CP_WAIT(1); }
        else         { CP_WAIT(0); }
        __syncthreads();
        const uint32_t base = smb + (ch & 1) * BUF_BYTES;

#pragma unroll
        for (int ks = 0; ks < 4; ks++) {
            uint32_t ah[4][4], al[4][4];
#pragma unroll
            for (int mt = 0; mt < 4; mt++) {
                const int r = wm + mt * 16 + a_row_in;
                const uint32_t col = (uint32_t)(ks * 32 + a_colsel * 16);
                const uint32_t addr = base + r * 128 + (col ^ ((r & 7) << 4));
                LDMX4(ah[mt], addr + OFF_A_HI);
                LDMX4(al[mt], addr + OFF_A_LO);
            }
            uint32_t bh[4][2];
#pragma unroll
            for (int nt = 0; nt < 4; nt++) {
                const int r = wn + nt * 8 + b_row_in;
                const uint32_t col = (uint32_t)(ks * 32 + b_colsel * 16);
                const uint32_t addr = base + r * 128 + (col ^ ((r & 7) << 4));
                LDMX2(bh[nt], addr + OFF_B_HI);
            }
#pragma unroll
            for (int mt = 0; mt < 4; mt++)
#pragma unroll
                for (int nt = 0; nt < 4; nt++) {
                    mma_f16(acc[mt][nt], ah[mt], bh[nt]);
                    mma_f16(acc[mt][nt], al[mt], bh[nt]);
                }
        }
        __syncthreads();
    }

#pragma unroll
    for (int mt = 0; mt < 4; mt++) {
        const int r0 = m0 + wm + mt * 16 + (lane >> 2);
        const float bv0 = bias[r0], bv1 = bias[r0 + 8];
#pragma unroll
        for (int nt = 0; nt < 4; nt++) {
            const int cn = n0 + wn + nt * 8 + (lane & 3) * 2;
            *(float2*)&Yb[(size_t)r0 * NT + cn] =
                make_float2(acc[mt][nt][0] + bv0, acc[mt][nt][1] + bv0);
            *(float2*)&Yb[(size_t)(r0 + 8) * NT + cn] =
                make_float2(acc[mt][nt][2] + bv1, acc[mt][nt][3] + bv1);
        }
    }
}

// Fused q+kv projection: grid (8, 24, NB). y<8 -> q (x input), y>=8 -> kv (c).
__global__ __launch_bounds__(256) void qkv_gemm_kernel(
    const float* __restrict__ q_b, const float* __restrict__ kv_b)
{
    extern __shared__ char sm[];
    const int b = blockIdx.z;
    const int yb = blockIdx.y;
    if (yb < 8) {
        gemm_tile_body(g_w_hi, g_w_lo,
                       g_a_h + XOFF + (size_t)b * NC * NT, q_b,
                       g_q + (size_t)b * NC * NT,
                       yb * 128, blockIdx.x * 128, sm);
    } else {
        gemm_tile_body(g_w_hi + 1024 * 1024, g_w_lo + 1024 * 1024,
                       g_a_h + COFF + (size_t)b * NC * NT, kv_b,
                       g_kv + (size_t)b * 2 * NC * NT,
                       (yb - 8) * 128, blockIdx.x * 128, sm);
    }
}

// Output projection: out = o_w @ att + o_b
__global__ __launch_bounds__(256) void o_gemm_kernel(
    const float* __restrict__ o_b, float* __restrict__ out)
{
    extern __shared__ char sm[];
    const int b = blockIdx.z;
    gemm_tile_body(g_w_hi + 3 * 1024 * 1024, g_w_lo + 3 * 1024 * 1024,
                   g_a_h + ATTOFF + (size_t)b * NC * NT, o_b,
                   out + (size_t)b * NC * NT,
                   blockIdx.y * 128, blockIdx.x * 128, sm);
}

// ---------------------------------------------------------------------------
// Register-resident FA2 attention, fp16 2-term split.
// Grid (T/128, NH, NB), 256 threads (8 warps). Q split 2-term (hi+lo frags),
// K/V hi-only. Softmax fully in registers; P split in registers.
// SMEM: Q staging 32KB first, then 2 x 16KB KV buffers (K 8KB | V 8KB).
// ---------------------------------------------------------------------------
#define KV_BUF 16384u
#define SMEM_ATT 32768

__global__ __launch_bounds__(256) void attn_mma_kernel()
{
    extern __shared__ char sm[];
    const uint32_t smb = smem_to_u32(sm);
    const int tid = threadIdx.x, wid = tid >> 5, lane = tid & 31;
    const int b = blockIdx.z, h = blockIdx.y;
    const int q0 = blockIdx.x * 128;
    const int z = b * NH + h;
    const int wm = wid * 16;

    // ---- stage Q (hi 16KB | lo 16KB), load frags, free smem ----
    {
        const __half* qhp = g_qkvh + QOFF + ((size_t)z * NT + q0) * 64;
        const __half* qlp = g_qlo + ((size_t)z * NT + q0) * 64;
        for (int idx = tid; idx < 1024; idx += 256) {
            const int row = idx >> 3, v = idx & 7;
            const uint32_t d = row * 128 + ((v * 16) ^ ((row & 7) << 4));
            *(uint4*)(sm + d)         = *((const uint4*)(qhp + row * 64) + v);
            *(uint4*)(sm + 16384 + d) = *((const uint4*)(qlp + row * 64) + v);
        }
    }
    __syncthreads();

    const int a_row = (lane & 7) + ((lane >> 3) & 1) * 8;
    const int a_cs  = (lane >> 4) & 1;
    uint32_t qh[4][4], ql[4][4];
#pragma unroll
    for (int ks = 0; ks < 4; ks++) {
        const int r = wm + a_row;
        const uint32_t addr =
            smb + r * 128 + ((uint32_t)(ks * 32 + a_cs * 16) ^ ((r & 7) << 4));
        LDMX4(qh[ks], addr);
        LDMX4(ql[ks], addr + 16384);
    }
    __syncthreads();   // all warps done reading Q staging

    // ---- KV staging (hi-only) ----
    const __half* kh_g = g_qkvh + KOFF + (size_t)z * NT * 64;
    const __half* vh_g = g_qkvh + VOFF + (size_t)z * NT * 64;

    auto stageKV = [&](int ch, int buf) {
        const uint32_t base = smb + buf * KV_BUF;
        const int k0 = ch * 64;
#pragma unroll
        for (int it = 0; it < 2; it++) {
            const int idx = tid + it * 256;       // 0..511
            const int row = idx >> 3, v = idx & 7;
            const uint32_t d = row * 128 + ((v * 16) ^ ((row & 7) << 4));
            const size_t go = (size_t)(k0 + row) * 64 + v * 8;
            CP_ASYNC16(base + d,        kh_g + go);
            CP_ASYNC16(base + 8192 + d, vh_g + go);
        }
        CP_COMMIT();
    };
    stageKV(0, 0);

    float m0 = -CUDART_INF_F, m1 = -CUDART_INF_F;
    float l0 = 0.f, l1 = 0.f;
    float oacc[8][4];
#pragma unroll
    for (int nt = 0; nt < 8; nt++)
#pragma unroll
        for (int i = 0; i < 4; i++) oacc[nt][i] = 0.f;

    const int b_row = lane & 7;
    const int b_cs  = (lane >> 3) & 1;

    for (int ch = 0; ch < 16; ch++) {
        if (ch < 15) { stageKV(ch + 1, (ch + 1) & 1); CP_WAIT(1); }
        else         { CP_WAIT(0); }
        __syncthreads();
        const uint32_t base = smb + (ch & 1) * KV_BUF;

        // ---- S = Q K^T (Q split, K hi): warp tile 16 rows x 64 keys ----
        float sacc[8][4];
#pragma unroll
        for (int nt = 0; nt < 8; nt++)
#pragma unroll
            for (int i = 0; i < 4; i++) sacc[nt][i] = 0.f;

#pragma unroll
        for (int ks = 0; ks < 4; ks++) {
#pragma unroll
            for (int nt = 0; nt < 8; nt++) {
                uint32_t bh[2];
                const int r = nt * 8 + b_row;
                const uint32_t addr =
                    base + r * 128 + ((uint32_t)(ks * 32 + b_cs * 16) ^ ((r & 7) << 4));
                LDMX2(bh, addr);
                mma_f16(sacc[nt], qh[ks], bh);
                mma_f16(sacc[nt], ql[ks], bh);
            }
        }

        // ---- in-register online softmax ----
        float mx0 = -CUDART_INF_F, mx1 = -CUDART_INF_F;
#pragma unroll
        for (int nt = 0; nt < 8; nt++) {
            sacc[nt][0] *= 0.125f; sacc[nt][1] *= 0.125f;
            sacc[nt][2] *= 0.125f; sacc[nt][3] *= 0.125f;
            mx0 = fmaxf(mx0, fmaxf(sacc[nt][0], sacc[nt][1]));
            mx1 = fmaxf(mx1, fmaxf(sacc[nt][2], sacc[nt][3]));
        }
        mx0 = fmaxf(mx0, __shfl_xor_sync(0xffffffffu, mx0, 1));
        mx0 = fmaxf(mx0, __shfl_xor_sync(0xffffffffu, mx0, 2));
        mx1 = fmaxf(mx1, __shfl_xor_sync(0xffffffffu, mx1, 1));
        mx1 = fmaxf(mx1, __shfl_xor_sync(0xffffffffu, mx1, 2));
        const float mn0 = fmaxf(m0, mx0), mn1 = fmaxf(m1, mx1);
        const float al0 = __expf(m0 - mn0), al1 = __expf(m1 - mn1);
        m0 = mn0; m1 = mn1;
        float ls0 = 0.f, ls1 = 0.f;
#pragma unroll
        for (int nt = 0; nt < 8; nt++) {
            sacc[nt][0] = __expf(sacc[nt][0] - mn0);
            sacc[nt][1] = __expf(sacc[nt][1] - mn0);
            sacc[nt][2] = __expf(sacc[nt][2] - mn1);
            sacc[nt][3] = __expf(sacc[nt][3] - mn1);
            ls0 += sacc[nt][0] + sacc[nt][1];
            ls1 += sacc[nt][2] + sacc[nt][3];
        }
        ls0 += __shfl_xor_sync(0xffffffffu, ls0, 1);
        ls0 += __shfl_xor_sync(0xffffffffu, ls0, 2);
        ls1 += __shfl_xor_sync(0xffffffffu, ls1, 1);
        ls1 += __shfl_xor_sync(0xffffffffu, ls1, 2);
        l0 = l0 * al0 + ls0;
        l1 = l1 * al1 + ls1;
#pragma unroll
        for (int nt = 0; nt < 8; nt++) {
            oacc[nt][0] *= al0; oacc[nt][1] *= al0;
            oacc[nt][2] *= al1; oacc[nt][3] *= al1;
        }

        // ---- O += P V (P split, V hi) ----
#pragma unroll
        for (int ksp = 0; ksp < 4; ksp++) {
            uint32_t ph[4], pl[4];
            split2h(sacc[2 * ksp][0],     sacc[2 * ksp][1],     ph[0], pl[0]);
            split2h(sacc[2 * ksp][2],     sacc[2 * ksp][3],     ph[1], pl[1]);
            split2h(sacc[2 * ksp + 1][0], sacc[2 * ksp + 1][1], ph[2], pl[2]);
            split2h(sacc[2 * ksp + 1][2], sacc[2 * ksp + 1][3], ph[3], pl[3]);
            const int k = ksp * 16 + (lane & 15);
#pragma unroll
            for (int nt = 0; nt < 8; nt++) {
                uint32_t vh[2];
                const uint32_t addr =
                    base + 8192 + k * 128 + ((uint32_t)(nt * 16) ^ ((k & 7) << 4));
                LDMX2T(vh, addr);
                mma_f16(oacc[nt], ph, vh);
                mma_f16(oacc[nt], pl, vh);
            }
        }
        __syncthreads();   // compute done before next stage overwrites
    }

    // ---- epilogue: normalize, write fp16 hi to att region ----
    const float il0 = 1.f / l0, il1 = 1.f / l1;
    const int r = wm + (lane >> 2);
    const size_t rowo = ATTOFF + (size_t)b * (NC * NT) +
                        (size_t)(q0 + r) * NC + h * 64;
#pragma unroll
    for (int nt = 0; nt < 8; nt++) {
        const int d = nt * 8 + (lane & 3) * 2;
        *(__half2*)(g_a_h + rowo + d) = __halves2half2(
            __float2half(oacc[nt][0] * il0), __float2half(oacc[nt][1] * il0));
        *(__half2*)(g_a_h + rowo + 8 * NC + d) = __halves2half2(
            __float2half(oacc[nt][2] * il1), __float2half(oacc[nt][3] * il1));
    }
}

// ---------------------------------------------------------------------------
extern "C" void kernel_launch(void* const* d_in, const int* in_sizes, int n_in,
                              void* d_out, int out_size)
{
    const float* x    = (const float*)d_in[0];
    const float* c    = (const float*)d_in[1];
    const float* q_w  = (const float*)d_in[2];
    const float* q_b  = (const float*)d_in[3];
    const float* kv_w = (const float*)d_in[4];
    const float* kv_b = (const float*)d_in[5];
    const float* o_w  = (const float*)d_in[6];
    const float* o_b  = (const float*)d_in[7];
    float* out = (float*)d_out;

    static bool attr_done = false;
    if (!attr_done) {
        cudaFuncSetAttribute(qkv_gemm_kernel, cudaFuncAttributeMaxDynamicSharedMemorySize, SMEM_MMA);
        cudaFuncSetAttribute(o_gemm_kernel, cudaFuncAttributeMaxDynamicSharedMemorySize, SMEM_MMA);
        cudaFuncSetAttribute(attn_mma_kernel, cudaFuncAttributeMaxDynamicSharedMemorySize, SMEM_ATT);
        attr_done = true;
    }

    // Split weights (q | kv | o)
    split_w_kernel<<<1024, 256>>>(q_w, 0, 1024 * 1024);
    split_w_kernel<<<1024, 256>>>(kv_w, 1024 * 1024, 2 * 1024 * 1024);
    split_w_kernel<<<1024, 256>>>(o_w, 3 * 1024 * 1024, 1024 * 1024);
    // Transpose activations x, c to [T][C] fp16 hi
    tsplit_kernel<<<dim3(32, 32, NB), dim3(32, 8)>>>(x, XOFF);
    tsplit_kernel<<<dim3(32, 32, NB), dim3(32, 8)>>>(c, COFF);
    // Fused q+kv projection (one launch, 768 CTAs)
    qkv_gemm_kernel<<<dim3(8, 24, NB), 256, SMEM_MMA>>>(q_b, kv_b);
    // RoPE + fp16 q/k/v
    qkv_prep_kernel<0><<<dim3(32, 2, NB * NH), dim3(32, 8)>>>();
    qkv_prep_kernel<1><<<dim3(32, 2, NB * NH), dim3(32, 8)>>>();
    qkv_prep_kernel<2><<<dim3(32, 2, NB * NH), dim3(32, 8)>>>();
    // register-resident FA2 attention (writes fp16 att activations)
    attn_mma_kernel<<<dim3(NT / 128, NH, NB), 256, SMEM_ATT>>>();
    // out = o_w @ att + o_b
    o_gemm_kernel<<<dim3(8, 8, NB), 256, SMEM_MMA>>>(o_b, out);
}

// round 10
// speedup vs baseline: 5.6544x; 1.4413x over previous
#include <cuda_runtime.h>
#include <cuda_fp16.h>
#include <math_constants.h>
#include <cstdint>

#define NB 4
#define NC 1024
#define NT 1024
#define NH 16
#define NDH 64
#define KDIM 1024

// ---------------------------------------------------------------------------
// Scratch (__device__ globals; allocation-free)
// ---------------------------------------------------------------------------
// Weights fp16 hi-only: [q(1M) | kv(2M) | o(1M)] elems
__device__ __align__(16) __half g_w_hi[4 * 1024 * 1024];
// Activations hi-only, [T][C] rows: [x(4M) | c(4M) | att(4M)] elems
__device__ __align__(16) __half g_a_h[12 * 1024 * 1024];
// RoPE'd q/k/v hi, [b][h][t][64] rows: [q(4M) | k(4M) | v(4M)]; q lo separate
__device__ __align__(16) __half g_qkvh[12 * 1024 * 1024];
__device__ __align__(16) __half g_qlo[4 * 1024 * 1024];

#define QOFF ((size_t)0)
#define KOFF ((size_t)4 * 1024 * 1024)
#define VOFF ((size_t)8 * 1024 * 1024)
#define XOFF ((size_t)0)
#define COFF ((size_t)4 * 1024 * 1024)
#define ATTOFF ((size_t)8 * 1024 * 1024)

// ---------------------------------------------------------------------------
// Base-ISA tensor helpers (sm_80+ features; compile for plain sm_100)
// ---------------------------------------------------------------------------
__device__ __forceinline__ uint32_t smem_to_u32(const void* p) {
    uint32_t a;
    asm("{ .reg .u64 t; cvta.to.shared.u64 t, %1; cvt.u32.u64 %0, t; }"
        : "=r"(a) : "l"(p));
    return a;
}
#define CP_ASYNC16(dst, src) \
    asm volatile("cp.async.cg.shared.global [%0], [%1], 16;" \
        :: "r"(dst), "l"(src) : "memory")
#define CP_COMMIT() asm volatile("cp.async.commit_group;" ::: "memory")
#define CP_WAIT(n)  asm volatile("cp.async.wait_group %0;" :: "n"(n) : "memory")
#define LDMX4(r, addr) \
    asm volatile("ldmatrix.sync.aligned.m8n8.x4.shared.b16 {%0,%1,%2,%3}, [%4];" \
        : "=r"((r)[0]), "=r"((r)[1]), "=r"((r)[2]), "=r"((r)[3]) : "r"(addr))
#define LDMX2(r, addr) \
    asm volatile("ldmatrix.sync.aligned.m8n8.x2.shared.b16 {%0,%1}, [%2];" \
        : "=r"((r)[0]), "=r"((r)[1]) : "r"(addr))
#define LDMX2T(r, addr) \
    asm volatile("ldmatrix.sync.aligned.m8n8.x2.trans.shared.b16 {%0,%1}, [%2];" \
        : "=r"((r)[0]), "=r"((r)[1]) : "r"(addr))

__device__ __forceinline__ void mma_f16(float* c, const uint32_t* a,
                                        const uint32_t* b) {
    asm volatile(
        "mma.sync.aligned.m16n8k16.row.col.f32.f16.f16.f32 "
        "{%0,%1,%2,%3}, {%4,%5,%6,%7}, {%8,%9}, {%0,%1,%2,%3};"
        : "+f"(c[0]), "+f"(c[1]), "+f"(c[2]), "+f"(c[3])
        : "r"(a[0]), "r"(a[1]), "r"(a[2]), "r"(a[3]), "r"(b[0]), "r"(b[1]));
}

// Split two floats into fp16 hi-pair and lo-pair (packed b16x2)
__device__ __forceinline__ void split2h(float a, float b, uint32_t& hp, uint32_t& lp) {
    __half ha = __float2half(a), hb = __float2half(b);
    __half2 hh = __halves2half2(ha, hb);
    __half2 ll = __halves2half2(__float2half(a - __half2float(ha)),
                                __float2half(b - __half2float(hb)));
    hp = *(uint32_t*)&hh;
    lp = *(uint32_t*)&ll;
}

// ---------------------------------------------------------------------------
// Weight convert: fp32 -> fp16 hi
// ---------------------------------------------------------------------------
__global__ __launch_bounds__(256) void conv_w_kernel(
    const float* __restrict__ src, size_t dst_off, int count)
{
    int stride = gridDim.x * blockDim.x;
    for (int i = blockIdx.x * blockDim.x + threadIdx.x; i < count; i += stride)
        g_w_hi[dst_off + i] = __float2half(src[i]);
}

// ---------------------------------------------------------------------------
// Fused activation transpose: x,c [C][T] fp32 -> [T][C] fp16 hi.
// Grid (32, 32, 8): z<4 -> x batch z; else c batch z-4.
// ---------------------------------------------------------------------------
__global__ __launch_bounds__(256) void tsplit2_kernel(
    const float* __restrict__ x, const float* __restrict__ c)
{
    __shared__ float tile[32][33];
    const int z = blockIdx.z;
    const float* src = (z < 4) ? x + (size_t)z * NC * NT
                               : c + (size_t)(z - 4) * NC * NT;
    const size_t db = (z < 4) ? XOFF + (size_t)z * NC * NT
                              : COFF + (size_t)(z - 4) * NC * NT;
    const int t0 = blockIdx.x * 32, c0 = blockIdx.y * 32;
    const int tx = threadIdx.x, ty = threadIdx.y;
#pragma unroll
    for (int i = 0; i < 4; i++)
        tile[ty + 8 * i][tx] = src[(size_t)(c0 + ty + 8 * i) * NT + t0 + tx];
    __syncthreads();
#pragma unroll
    for (int i = 0; i < 4; i++)
        g_a_h[db + (size_t)(t0 + ty + 8 * i) * NC + c0 + tx] =
            __float2half(tile[tx][ty + 8 * i]);
}

// ---------------------------------------------------------------------------
// fp16 hi-only GEMM mainloop: acc = W[m0..][.] * X[n0..][.]^T
// 128x128 CTA tile, 8 warps, K-chunk 64, cp.async double buffer,
// 2 staged arrays (A 16KB | B 16KB) per buffer.
// ---------------------------------------------------------------------------
#define BUF_BYTES 32768u
#define OFF_B 16384u

__device__ __forceinline__ void gemm_mainloop(
    const __half* __restrict__ Wh, const __half* __restrict__ Xh,
    char* sm, int m0, int n0, float acc[4][4][4])
{
    const uint32_t smb = smem_to_u32(sm);
    const int tid = threadIdx.x;
    const int wid = tid >> 5, lane = tid & 31;
    const int wm = (wid >> 2) * 64;
    const int wn = (wid & 3) * 32;

#pragma unroll
    for (int mt = 0; mt < 4; mt++)
#pragma unroll
        for (int nt = 0; nt < 4; nt++)
#pragma unroll
            for (int i = 0; i < 4; i++) acc[mt][nt][i] = 0.f;

    auto stage = [&](int ch, int buf) {
        const uint32_t base = smb + buf * BUF_BYTES;
        const int k0 = ch * 64;
#pragma unroll
        for (int it = 0; it < 4; it++) {
            const int idx = tid + it * 256;
            const int row = idx >> 3, v = idx & 7;
            const uint32_t dst = base + row * 128 + ((v * 16) ^ ((row & 7) << 4));
            CP_ASYNC16(dst,         Wh + (size_t)(m0 + row) * KDIM + k0 + v * 8);
            CP_ASYNC16(dst + OFF_B, Xh + (size_t)(n0 + row) * KDIM + k0 + v * 8);
        }
        CP_COMMIT();
    };

    stage(0, 0);

    const int a_row_in = (lane & 7) + ((lane >> 3) & 1) * 8;
    const int a_colsel = (lane >> 4) & 1;
    const int b_row_in = lane & 7;
    const int b_colsel = (lane >> 3) & 1;

    for (int ch = 0; ch < 16; ch++) {
        if (ch < 15) { stage(ch + 1, (ch + 1) & 1); CP_WAIT(1); }
        else         { CP_WAIT(0); }
        __syncthreads();
        const uint32_t base = smb + (ch & 1) * BUF_BYTES;

#pragma unroll
        for (int ks = 0; ks < 4; ks++) {
            uint32_t ah[4][4];
#pragma unroll
            for (int mt = 0; mt < 4; mt++) {
                const int r = wm + mt * 16 + a_row_in;
                const uint32_t col = (uint32_t)(ks * 32 + a_colsel * 16);
                LDMX4(ah[mt], base + r * 128 + (col ^ ((r & 7) << 4)));
            }
            uint32_t bh[4][2];
#pragma unroll
            for (int nt = 0; nt < 4; nt++) {
                const int r = wn + nt * 8 + b_row_in;
                const uint32_t col = (uint32_t)(ks * 32 + b_colsel * 16);
                LDMX2(bh[nt], base + OFF_B + r * 128 + (col ^ ((r & 7) << 4)));
            }
#pragma unroll
            for (int mt = 0; mt < 4; mt++)
#pragma unroll
                for (int nt = 0; nt < 4; nt++)
                    mma_f16(acc[mt][nt], ah[mt], bh[nt]);
        }
        __syncthreads();
    }
}

// ---------------------------------------------------------------------------
// Fused q+kv projection with RoPE + fp16 epilogue writing [b][h][t][64].
// Grid (8, 24, NB): yb<8 -> q (x input); yb>=8 -> kv (c input).
// Warp M-tile (64 rows) == one head, so RoPE pair (j, j+16) lives in
// acc[0]/acc[1] of the same thread. Epilogue stages [t][c] via padded smem.
// SMEM: max(2*32KB mainloop, 2*34816 epilogue) = 69632.
// ---------------------------------------------------------------------------
#define SMEM_QKV 69632

__global__ __launch_bounds__(256) void qkv_gemm_kernel(
    const float* __restrict__ q_b, const float* __restrict__ kv_b)
{
    extern __shared__ char sm[];
    const int b = blockIdx.z, yb = blockIdx.y;
    const int n0 = blockIdx.x * 128;
    const bool isQ = (yb < 8);
    const int m0 = isQ ? yb * 128 : (yb - 8) * 128;
    const __half* W = isQ ? g_w_hi : g_w_hi + 1024 * 1024;
    const __half* X = g_a_h + (isQ ? XOFF : COFF) + (size_t)b * NC * NT;
    const float* bias = isQ ? q_b : kv_b;

    float acc[4][4][4];
    gemm_mainloop(W, X, sm, m0, n0, acc);

    const int tid = threadIdx.x, wid = tid >> 5, lane = tid & 31;
    const int wm = (wid >> 2) * 64, wn = (wid & 3) * 32;
    const bool isV = (!isQ) && (m0 >= 1024);

    // bias (before RoPE, matching reference)
#pragma unroll
    for (int mt = 0; mt < 4; mt++) {
        const int r0 = wm + mt * 16 + (lane >> 2);
        const float b0 = bias[m0 + r0], b1 = bias[m0 + r0 + 8];
#pragma unroll
        for (int nt = 0; nt < 4; nt++) {
            acc[mt][nt][0] += b0; acc[mt][nt][1] += b0;
            acc[mt][nt][2] += b1; acc[mt][nt][3] += b1;
        }
    }

    // RoPE on head dims [0,32): pair (j, j+16) = (acc[0], acc[1]) same thread
    if (!isV) {
        const float LN = 0.57564627324851145f;  // ln(10000)/16
        const int j0 = lane >> 2;
        const float th0 = __expf(-(float)j0 * LN);
        const float th1 = __expf(-(float)(j0 + 8) * LN);
#pragma unroll
        for (int nt = 0; nt < 4; nt++) {
#pragma unroll
            for (int i = 0; i < 4; i++) {
                const int t = n0 + wn + nt * 8 + (lane & 3) * 2 + (i & 1);
                const float th = (i >= 2) ? th1 : th0;
                float sn, cs;
                sincosf((float)t * th, &sn, &cs);
                const float a0 = acc[0][nt][i], a1 = acc[1][nt][i];
                acc[0][nt][i] = a0 * cs - a1 * sn;
                acc[1][nt][i] = a1 * cs + a0 * sn;
            }
        }
    }

    // stage [t][c] (pad 136) in smem; hi always, lo for q
    __half* s_hi = (__half*)sm;
    __half* s_lo = (__half*)(sm + 34816);
#pragma unroll
    for (int mt = 0; mt < 4; mt++) {
#pragma unroll
        for (int nt = 0; nt < 4; nt++) {
#pragma unroll
            for (int i = 0; i < 4; i++) {
                const int r = wm + mt * 16 + (lane >> 2) + ((i >> 1) << 3);
                const int col = wn + nt * 8 + (lane & 3) * 2 + (i & 1);
                const float v = acc[mt][nt][i];
                const __half hh = __float2half(v);
                s_hi[col * 136 + r] = hh;
                if (isQ) s_lo[col * 136 + r] = __float2half(v - __half2float(hh));
            }
        }
    }
    __syncthreads();

    // coalesced copy-out: 128 t x 128 c (2 heads x 64)
    const size_t roff = isQ ? QOFF : (m0 < 1024 ? KOFF : VOFF);
    const int hd0 = (m0 & 1023) >> 6;
    const int z0 = b * NH + hd0;
    for (int idx = tid; idx < 128 * 16; idx += 256) {
        const int t = idx >> 4, u = idx & 15;
        const int cc = u * 8;
        const int hd = cc >> 6, cl = cc & 63;
        const size_t go = ((size_t)(z0 + hd) * NT + (n0 + t)) * 64 + cl;
        *(uint4*)(g_qkvh + roff + go) = *(uint4*)(s_hi + t * 136 + cc);
        if (isQ) *(uint4*)(g_qlo + go) = *(uint4*)(s_lo + t * 136 + cc);
    }
}

// ---------------------------------------------------------------------------
// Output projection: out = o_w @ att + o_b (fp32 out)
// ---------------------------------------------------------------------------
#define SMEM_OG (2 * 32768)

__global__ __launch_bounds__(256) void o_gemm_kernel(
    const float* __restrict__ o_b, float* __restrict__ out)
{
    extern __shared__ char sm[];
    const int b = blockIdx.z;
    const int m0 = blockIdx.y * 128, n0 = blockIdx.x * 128;

    float acc[4][4][4];
    gemm_mainloop(g_w_hi + 3 * 1024 * 1024,
                  g_a_h + ATTOFF + (size_t)b * NC * NT, sm, m0, n0, acc);

    const int tid = threadIdx.x, wid = tid >> 5, lane = tid & 31;
    const int wm = (wid >> 2) * 64, wn = (wid & 3) * 32;
    float* Yb = out + (size_t)b * NC * NT;

#pragma unroll
    for (int mt = 0; mt < 4; mt++) {
        const int r0 = m0 + wm + mt * 16 + (lane >> 2);
        const float bv0 = o_b[r0], bv1 = o_b[r0 + 8];
#pragma unroll
        for (int nt = 0; nt < 4; nt++) {
            const int cn = n0 + wn + nt * 8 + (lane & 3) * 2;
            *(float2*)&Yb[(size_t)r0 * NT + cn] =
                make_float2(acc[mt][nt][0] + bv0, acc[mt][nt][1] + bv0);
            *(float2*)&Yb[(size_t)(r0 + 8) * NT + cn] =
                make_float2(acc[mt][nt][2] + bv1, acc[mt][nt][3] + bv1);
        }
    }
}

// ---------------------------------------------------------------------------
// Register-resident FA2 attention, fp16 (Q 2-term, K/V hi, P 2-term).
// Grid (T/128, NH, NB), 256 threads (8 warps). Unchanged from R9.
// ---------------------------------------------------------------------------
#define KV_BUF 16384u
#define SMEM_ATT 32768

__global__ __launch_bounds__(256) void attn_mma_kernel()
{
    extern __shared__ char sm[];
    const uint32_t smb = smem_to_u32(sm);
    const int tid = threadIdx.x, wid = tid >> 5, lane = tid & 31;
    const int b = blockIdx.z, h = blockIdx.y;
    const int q0 = blockIdx.x * 128;
    const int z = b * NH + h;
    const int wm = wid * 16;

    // ---- stage Q (hi 16KB | lo 16KB), load frags, free smem ----
    {
        const __half* qhp = g_qkvh + QOFF + ((size_t)z * NT + q0) * 64;
        const __half* qlp = g_qlo + ((size_t)z * NT + q0) * 64;
        for (int idx = tid; idx < 1024; idx += 256) {
            const int row = idx >> 3, v = idx & 7;
            const uint32_t d = row * 128 + ((v * 16) ^ ((row & 7) << 4));
            *(uint4*)(sm + d)         = *((const uint4*)(qhp + row * 64) + v);
            *(uint4*)(sm + 16384 + d) = *((const uint4*)(qlp + row * 64) + v);
        }
    }
    __syncthreads();

    const int a_row = (lane & 7) + ((lane >> 3) & 1) * 8;
    const int a_cs  = (lane >> 4) & 1;
    uint32_t qh[4][4], ql[4][4];
#pragma unroll
    for (int ks = 0; ks < 4; ks++) {
        const int r = wm + a_row;
        const uint32_t addr =
            smb + r * 128 + ((uint32_t)(ks * 32 + a_cs * 16) ^ ((r & 7) << 4));
        LDMX4(qh[ks], addr);
        LDMX4(ql[ks], addr + 16384);
    }
    __syncthreads();   // all warps done reading Q staging

    // ---- KV staging (hi-only) ----
    const __half* kh_g = g_qkvh + KOFF + (size_t)z * NT * 64;
    const __half* vh_g = g_qkvh + VOFF + (size_t)z * NT * 64;

    auto stageKV = [&](int ch, int buf) {
        const uint32_t base = smb + buf * KV_BUF;
        const int k0 = ch * 64;
#pragma unroll
        for (int it = 0; it < 2; it++) {
            const int idx = tid + it * 256;       // 0..511
            const int row = idx >> 3, v = idx & 7;
            const uint32_t d = row * 128 + ((v * 16) ^ ((row & 7) << 4));
            const size_t go = (size_t)(k0 + row) * 64 + v * 8;
            CP_ASYNC16(base + d,        kh_g + go);
            CP_ASYNC16(base + 8192 + d, vh_g + go);
        }
        CP_COMMIT();
    };
    stageKV(0, 0);

    float m0 = -CUDART_INF_F, m1 = -CUDART_INF_F;
    float l0 = 0.f, l1 = 0.f;
    float oacc[8][4];
#pragma unroll
    for (int nt = 0; nt < 8; nt++)
#pragma unroll
        for (int i = 0; i < 4; i++) oacc[nt][i] = 0.f;

    const int b_row = lane & 7;
    const int b_cs  = (lane >> 3) & 1;

    for (int ch = 0; ch < 16; ch++) {
        if (ch < 15) { stageKV(ch + 1, (ch + 1) & 1); CP_WAIT(1); }
        else         { CP_WAIT(0); }
        __syncthreads();
        const uint32_t base = smb + (ch & 1) * KV_BUF;

        // ---- S = Q K^T (Q split, K hi) ----
        float sacc[8][4];
#pragma unroll
        for (int nt = 0; nt < 8; nt++)
#pragma unroll
            for (int i = 0; i < 4; i++) sacc[nt][i] = 0.f;

#pragma unroll
        for (int ks = 0; ks < 4; ks++) {
#pragma unroll
            for (int nt = 0; nt < 8; nt++) {
                uint32_t bh[2];
                const int r = nt * 8 + b_row;
                const uint32_t addr =
                    base + r * 128 + ((uint32_t)(ks * 32 + b_cs * 16) ^ ((r & 7) << 4));
                LDMX2(bh, addr);
                mma_f16(sacc[nt], qh[ks], bh);
                mma_f16(sacc[nt], ql[ks], bh);
            }
        }

        // ---- in-register online softmax ----
        float mx0 = -CUDART_INF_F, mx1 = -CUDART_INF_F;
#pragma unroll
        for (int nt = 0; nt < 8; nt++) {
            sacc[nt][0] *= 0.125f; sacc[nt][1] *= 0.125f;
            sacc[nt][2] *= 0.125f; sacc[nt][3] *= 0.125f;
            mx0 = fmaxf(mx0, fmaxf(sacc[nt][0], sacc[nt][1]));
            mx1 = fmaxf(mx1, fmaxf(sacc[nt][2], sacc[nt][3]));
        }
        mx0 = fmaxf(mx0, __shfl_xor_sync(0xffffffffu, mx0, 1));
        mx0 = fmaxf(mx0, __shfl_xor_sync(0xffffffffu, mx0, 2));
        mx1 = fmaxf(mx1, __shfl_xor_sync(0xffffffffu, mx1, 1));
        mx1 = fmaxf(mx1, __shfl_xor_sync(0xffffffffu, mx1, 2));
        const float mn0 = fmaxf(m0, mx0), mn1 = fmaxf(m1, mx1);
        const float al0 = __expf(m0 - mn0), al1 = __expf(m1 - mn1);
        m0 = mn0; m1 = mn1;
        float ls0 = 0.f, ls1 = 0.f;
#pragma unroll
        for (int nt = 0; nt < 8; nt++) {
            sacc[nt][0] = __expf(sacc[nt][0] - mn0);
            sacc[nt][1] = __expf(sacc[nt][1] - mn0);
            sacc[nt][2] = __expf(sacc[nt][2] - mn1);
            sacc[nt][3] = __expf(sacc[nt][3] - mn1);
            ls0 += sacc[nt][0] + sacc[nt][1];
            ls1 += sacc[nt][2] + sacc[nt][3];
        }
        ls0 += __shfl_xor_sync(0xffffffffu, ls0, 1);
        ls0 += __shfl_xor_sync(0xffffffffu, ls0, 2);
        ls1 += __shfl_xor_sync(0xffffffffu, ls1, 1);
        ls1 += __shfl_xor_sync(0xffffffffu, ls1, 2);
        l0 = l0 * al0 + ls0;
        l1 = l1 * al1 + ls1;
#pragma unroll
        for (int nt = 0; nt < 8; nt++) {
            oacc[nt][0] *= al0; oacc[nt][1] *= al0;
            oacc[nt][2] *= al1; oacc[nt][3] *= al1;
        }

        // ---- O += P V (P split, V hi) ----
#pragma unroll
        for (int ksp = 0; ksp < 4; ksp++) {
            uint32_t ph[4], pl[4];
            split2h(sacc[2 * ksp][0],     sacc[2 * ksp][1],     ph[0], pl[0]);
            split2h(sacc[2 * ksp][2],     sacc[2 * ksp][3],     ph[1], pl[1]);
            split2h(sacc[2 * ksp + 1][0], sacc[2 * ksp + 1][1], ph[2], pl[2]);
            split2h(sacc[2 * ksp + 1][2], sacc[2 * ksp + 1][3], ph[3], pl[3]);
            const int k = ksp * 16 + (lane & 15);
#pragma unroll
            for (int nt = 0; nt < 8; nt++) {
                uint32_t vh[2];
                const uint32_t addr =
                    base + 8192 + k * 128 + ((uint32_t)(nt * 16) ^ ((k & 7) << 4));
                LDMX2T(vh, addr);
                mma_f16(oacc[nt], ph, vh);
                mma_f16(oacc[nt], pl, vh);
            }
        }
        __syncthreads();   // compute done before next stage overwrites
    }

    // ---- epilogue: normalize, write fp16 hi to att region ----
    const float il0 = 1.f / l0, il1 = 1.f / l1;
    const int r = wm + (lane >> 2);
    const size_t rowo = ATTOFF + (size_t)b * (NC * NT) +
                        (size_t)(q0 + r) * NC + h * 64;
#pragma unroll
    for (int nt = 0; nt < 8; nt++) {
        const int d = nt * 8 + (lane & 3) * 2;
        *(__half2*)(g_a_h + rowo + d) = __halves2half2(
            __float2half(oacc[nt][0] * il0), __float2half(oacc[nt][1] * il0));
        *(__half2*)(g_a_h + rowo + 8 * NC + d) = __halves2half2(
            __float2half(oacc[nt][2] * il1), __float2half(oacc[nt][3] * il1));
    }
}

// ---------------------------------------------------------------------------
extern "C" void kernel_launch(void* const* d_in, const int* in_sizes, int n_in,
                              void* d_out, int out_size)
{
    const float* x    = (const float*)d_in[0];
    const float* c    = (const float*)d_in[1];
    const float* q_w  = (const float*)d_in[2];
    const float* q_b  = (const float*)d_in[3];
    const float* kv_w = (const float*)d_in[4];
    const float* kv_b = (const float*)d_in[5];
    const float* o_w  = (const float*)d_in[6];
    const float* o_b  = (const float*)d_in[7];
    float* out = (float*)d_out;

    static bool attr_done = false;
    if (!attr_done) {
        cudaFuncSetAttribute(qkv_gemm_kernel, cudaFuncAttributeMaxDynamicSharedMemorySize, SMEM_QKV);
        cudaFuncSetAttribute(o_gemm_kernel, cudaFuncAttributeMaxDynamicSharedMemorySize, SMEM_OG);
        cudaFuncSetAttribute(attn_mma_kernel, cudaFuncAttributeMaxDynamicSharedMemorySize, SMEM_ATT);
        attr_done = true;
    }

    // Convert weights to fp16 hi (q | kv | o)
    conv_w_kernel<<<512, 256>>>(q_w, 0, 1024 * 1024);
    conv_w_kernel<<<512, 256>>>(kv_w, 1024 * 1024, 2 * 1024 * 1024);
    conv_w_kernel<<<512, 256>>>(o_w, 3 * 1024 * 1024, 1024 * 1024);
    // Fused transpose of x and c to [T][C] fp16
    tsplit2_kernel<<<dim3(32, 32, 2 * NB), dim3(32, 8)>>>(x, c);
    // Fused q+kv projection with RoPE epilogue (writes g_qkvh/g_qlo directly)
    qkv_gemm_kernel<<<dim3(8, 24, NB), 256, SMEM_QKV>>>(q_b, kv_b);
    // register-resident FA2 attention (writes fp16 att activations)
    attn_mma_kernel<<<dim3(NT / 128, NH, NB), 256, SMEM_ATT>>>();
    // out = o_w @ att + o_b
    o_gemm_kernel<<<dim3(8, 8, NB), 256, SMEM_OG>>>(o_b, out);
}

// round 11
// speedup vs baseline: 7.1894x; 1.2715x over previous
#include <cuda_runtime.h>
#include <cuda_fp16.h>
#include <math_constants.h>
#include <cstdint>

#define NB 4
#define NC 1024
#define NT 1024
#define NH 16
#define NDH 64
#define KDIM 1024

// ---------------------------------------------------------------------------
// Scratch (__device__ globals; allocation-free)
// ---------------------------------------------------------------------------
// Weights fp16: [q(1M) | kv(2M) | o(1M)] elems
__device__ __align__(16) __half g_w_hi[4 * 1024 * 1024];
// Activations fp16, [T][C] rows: [x(4M) | c(4M) | att(4M)] elems
__device__ __align__(16) __half g_a_h[12 * 1024 * 1024];
// RoPE'd q/k/v fp16, [b][h][t][64] rows: [q(4M) | k(4M) | v(4M)]
__device__ __align__(16) __half g_qkvh[12 * 1024 * 1024];

#define QOFF ((size_t)0)
#define KOFF ((size_t)4 * 1024 * 1024)
#define VOFF ((size_t)8 * 1024 * 1024)
#define XOFF ((size_t)0)
#define COFF ((size_t)4 * 1024 * 1024)
#define ATTOFF ((size_t)8 * 1024 * 1024)

// ---------------------------------------------------------------------------
// Base-ISA tensor helpers (sm_80+ features; compile for plain sm_100)
// ---------------------------------------------------------------------------
__device__ __forceinline__ uint32_t smem_to_u32(const void* p) {
    uint32_t a;
    asm("{ .reg .u64 t; cvta.to.shared.u64 t, %1; cvt.u32.u64 %0, t; }"
        : "=r"(a) : "l"(p));
    return a;
}
#define CP_ASYNC16(dst, src) \
    asm volatile("cp.async.cg.shared.global [%0], [%1], 16;" \
        :: "r"(dst), "l"(src) : "memory")
#define CP_COMMIT() asm volatile("cp.async.commit_group;" ::: "memory")
#define CP_WAIT(n)  asm volatile("cp.async.wait_group %0;" :: "n"(n) : "memory")
#define LDMX4(r, addr) \
    asm volatile("ldmatrix.sync.aligned.m8n8.x4.shared.b16 {%0,%1,%2,%3}, [%4];" \
        : "=r"((r)[0]), "=r"((r)[1]), "=r"((r)[2]), "=r"((r)[3]) : "r"(addr))
#define LDMX2(r, addr) \
    asm volatile("ldmatrix.sync.aligned.m8n8.x2.shared.b16 {%0,%1}, [%2];" \
        : "=r"((r)[0]), "=r"((r)[1]) : "r"(addr))
#define LDMX2T(r, addr) \
    asm volatile("ldmatrix.sync.aligned.m8n8.x2.trans.shared.b16 {%0,%1}, [%2];" \
        : "=r"((r)[0]), "=r"((r)[1]) : "r"(addr))

__device__ __forceinline__ void mma_f16(float* c, const uint32_t* a,
                                        const uint32_t* b) {
    asm volatile(
        "mma.sync.aligned.m16n8k16.row.col.f32.f16.f16.f32 "
        "{%0,%1,%2,%3}, {%4,%5,%6,%7}, {%8,%9}, {%0,%1,%2,%3};"
        : "+f"(c[0]), "+f"(c[1]), "+f"(c[2]), "+f"(c[3])
        : "r"(a[0]), "r"(a[1]), "r"(a[2]), "r"(a[3]), "r"(b[0]), "r"(b[1]));
}

__device__ __forceinline__ uint32_t pack2h(float a, float b) {
    __half2 h = __halves2half2(__float2half(a), __float2half(b));
    return *(uint32_t*)&h;
}

// ---------------------------------------------------------------------------
// Weight convert (all three in one launch): fp32 -> fp16
// ---------------------------------------------------------------------------
__global__ __launch_bounds__(256) void conv_w_kernel(
    const float* __restrict__ qw, const float* __restrict__ kvw,
    const float* __restrict__ ow)
{
    const int stride = gridDim.x * blockDim.x;
    const int M1 = 1024 * 1024, M3 = 3 * 1024 * 1024, M4 = 4 * 1024 * 1024;
    for (int i = blockIdx.x * blockDim.x + threadIdx.x; i < M4; i += stride) {
        float v;
        if (i < M1)      v = qw[i];
        else if (i < M3) v = kvw[i - M1];
        else             v = ow[i - M3];
        g_w_hi[i] = __float2half(v);
    }
}

// ---------------------------------------------------------------------------
// Fused activation transpose: x,c [C][T] fp32 -> [T][C] fp16.
// Grid (32, 32, 8): z<4 -> x batch z; else c batch z-4.
// ---------------------------------------------------------------------------
__global__ __launch_bounds__(256) void tsplit2_kernel(
    const float* __restrict__ x, const float* __restrict__ c)
{
    __shared__ float tile[32][33];
    const int z = blockIdx.z;
    const float* src = (z < 4) ? x + (size_t)z * NC * NT
                               : c + (size_t)(z - 4) * NC * NT;
    const size_t db = (z < 4) ? XOFF + (size_t)z * NC * NT
                              : COFF + (size_t)(z - 4) * NC * NT;
    const int t0 = blockIdx.x * 32, c0 = blockIdx.y * 32;
    const int tx = threadIdx.x, ty = threadIdx.y;
#pragma unroll
    for (int i = 0; i < 4; i++)
        tile[ty + 8 * i][tx] = src[(size_t)(c0 + ty + 8 * i) * NT + t0 + tx];
    __syncthreads();
#pragma unroll
    for (int i = 0; i < 4; i++)
        g_a_h[db + (size_t)(t0 + ty + 8 * i) * NC + c0 + tx] =
            __float2half(tile[tx][ty + 8 * i]);
}

// ---------------------------------------------------------------------------
// fp16 GEMM mainloop: acc = W[m0..][.] * X[n0..][.]^T
// 128x128 CTA tile, 8 warps, K-chunk 64, cp.async double buffer.
// ---------------------------------------------------------------------------
#define BUF_BYTES 32768u
#define OFF_B 16384u

__device__ __forceinline__ void gemm_mainloop(
    const __half* __restrict__ Wh, const __half* __restrict__ Xh,
    char* sm, int m0, int n0, float acc[4][4][4])
{
    const uint32_t smb = smem_to_u32(sm);
    const int tid = threadIdx.x;
    const int wid = tid >> 5, lane = tid & 31;
    const int wm = (wid >> 2) * 64;
    const int wn = (wid & 3) * 32;

#pragma unroll
    for (int mt = 0; mt < 4; mt++)
#pragma unroll
        for (int nt = 0; nt < 4; nt++)
#pragma unroll
            for (int i = 0; i < 4; i++) acc[mt][nt][i] = 0.f;

    auto stage = [&](int ch, int buf) {
        const uint32_t base = smb + buf * BUF_BYTES;
        const int k0 = ch * 64;
#pragma unroll
        for (int it = 0; it < 4; it++) {
            const int idx = tid + it * 256;
            const int row = idx >> 3, v = idx & 7;
            const uint32_t dst = base + row * 128 + ((v * 16) ^ ((row & 7) << 4));
            CP_ASYNC16(dst,         Wh + (size_t)(m0 + row) * KDIM + k0 + v * 8);
            CP_ASYNC16(dst + OFF_B, Xh + (size_t)(n0 + row) * KDIM + k0 + v * 8);
        }
        CP_COMMIT();
    };

    stage(0, 0);

    const int a_row_in = (lane & 7) + ((lane >> 3) & 1) * 8;
    const int a_colsel = (lane >> 4) & 1;
    const int b_row_in = lane & 7;
    const int b_colsel = (lane >> 3) & 1;

    for (int ch = 0; ch < 16; ch++) {
        if (ch < 15) { stage(ch + 1, (ch + 1) & 1); CP_WAIT(1); }
        else         { CP_WAIT(0); }
        __syncthreads();
        const uint32_t base = smb + (ch & 1) * BUF_BYTES;

#pragma unroll
        for (int ks = 0; ks < 4; ks++) {
            uint32_t ah[4][4];
#pragma unroll
            for (int mt = 0; mt < 4; mt++) {
                const int r = wm + mt * 16 + a_row_in;
                const uint32_t col = (uint32_t)(ks * 32 + a_colsel * 16);
                LDMX4(ah[mt], base + r * 128 + (col ^ ((r & 7) << 4)));
            }
            uint32_t bh[4][2];
#pragma unroll
            for (int nt = 0; nt < 4; nt++) {
                const int r = wn + nt * 8 + b_row_in;
                const uint32_t col = (uint32_t)(ks * 32 + b_colsel * 16);
                LDMX2(bh[nt], base + OFF_B + r * 128 + (col ^ ((r & 7) << 4)));
            }
#pragma unroll
            for (int mt = 0; mt < 4; mt++)
#pragma unroll
                for (int nt = 0; nt < 4; nt++)
                    mma_f16(acc[mt][nt], ah[mt], bh[nt]);
        }
        __syncthreads();
    }
}

// ---------------------------------------------------------------------------
// Fused q+kv projection with RoPE + fp16 epilogue writing [b][h][t][64].
// Grid (8, 24, NB): yb<8 -> q (x input); yb>=8 -> kv (c input).
// Warp M-tile (64 rows) == one head; RoPE pair (j, j+16) in acc[0]/acc[1].
// ---------------------------------------------------------------------------
#define SMEM_QKV 65536

__global__ __launch_bounds__(256) void qkv_gemm_kernel(
    const float* __restrict__ q_b, const float* __restrict__ kv_b)
{
    extern __shared__ char sm[];
    const int b = blockIdx.z, yb = blockIdx.y;
    const int n0 = blockIdx.x * 128;
    const bool isQ = (yb < 8);
    const int m0 = isQ ? yb * 128 : (yb - 8) * 128;
    const __half* W = isQ ? g_w_hi : g_w_hi + 1024 * 1024;
    const __half* X = g_a_h + (isQ ? XOFF : COFF) + (size_t)b * NC * NT;
    const float* bias = isQ ? q_b : kv_b;

    float acc[4][4][4];
    gemm_mainloop(W, X, sm, m0, n0, acc);

    const int tid = threadIdx.x, wid = tid >> 5, lane = tid & 31;
    const int wm = (wid >> 2) * 64, wn = (wid & 3) * 32;
    const bool isV = (!isQ) && (m0 >= 1024);

    // bias (before RoPE, matching reference)
#pragma unroll
    for (int mt = 0; mt < 4; mt++) {
        const int r0 = wm + mt * 16 + (lane >> 2);
        const float b0 = bias[m0 + r0], b1 = bias[m0 + r0 + 8];
#pragma unroll
        for (int nt = 0; nt < 4; nt++) {
            acc[mt][nt][0] += b0; acc[mt][nt][1] += b0;
            acc[mt][nt][2] += b1; acc[mt][nt][3] += b1;
        }
    }

    // RoPE on head dims [0,32): pair (j, j+16) = (acc[0], acc[1]) same thread
    if (!isV) {
        const float LN = 0.57564627324851145f;  // ln(10000)/16
        const int j0 = lane >> 2;
        const float th0 = __expf(-(float)j0 * LN);
        const float th1 = __expf(-(float)(j0 + 8) * LN);
#pragma unroll
        for (int nt = 0; nt < 4; nt++) {
#pragma unroll
            for (int i = 0; i < 4; i++) {
                const int t = n0 + wn + nt * 8 + (lane & 3) * 2 + (i & 1);
                const float th = (i >= 2) ? th1 : th0;
                float sn, cs;
                sincosf((float)t * th, &sn, &cs);
                const float a0 = acc[0][nt][i], a1 = acc[1][nt][i];
                acc[0][nt][i] = a0 * cs - a1 * sn;
                acc[1][nt][i] = a1 * cs + a0 * sn;
            }
        }
    }

    // stage [t][c] (pad 136) in smem as fp16
    __half* s_hi = (__half*)sm;
#pragma unroll
    for (int mt = 0; mt < 4; mt++) {
#pragma unroll
        for (int nt = 0; nt < 4; nt++) {
#pragma unroll
            for (int i = 0; i < 4; i++) {
                const int r = wm + mt * 16 + (lane >> 2) + ((i >> 1) << 3);
                const int col = wn + nt * 8 + (lane & 3) * 2 + (i & 1);
                s_hi[col * 136 + r] = __float2half(acc[mt][nt][i]);
            }
        }
    }
    __syncthreads();

    // coalesced copy-out: 128 t x 128 c (2 heads x 64)
    const size_t roff = isQ ? QOFF : (m0 < 1024 ? KOFF : VOFF);
    const int hd0 = (m0 & 1023) >> 6;
    const int z0 = b * NH + hd0;
    for (int idx = tid; idx < 128 * 16; idx += 256) {
        const int t = idx >> 4, u = idx & 15;
        const int cc = u * 8;
        const int hd = cc >> 6, cl = cc & 63;
        const size_t go = ((size_t)(z0 + hd) * NT + (n0 + t)) * 64 + cl;
        *(uint4*)(g_qkvh + roff + go) = *(uint4*)(s_hi + t * 136 + cc);
    }
}

// ---------------------------------------------------------------------------
// Output projection: out = o_w @ att + o_b (fp32 out)
// ---------------------------------------------------------------------------
#define SMEM_OG (2 * 32768)

__global__ __launch_bounds__(256) void o_gemm_kernel(
    const float* __restrict__ o_b, float* __restrict__ out)
{
    extern __shared__ char sm[];
    const int b = blockIdx.z;
    const int m0 = blockIdx.y * 128, n0 = blockIdx.x * 128;

    float acc[4][4][4];
    gemm_mainloop(g_w_hi + 3 * 1024 * 1024,
                  g_a_h + ATTOFF + (size_t)b * NC * NT, sm, m0, n0, acc);

    const int tid = threadIdx.x, wid = tid >> 5, lane = tid & 31;
    const int wm = (wid >> 2) * 64, wn = (wid & 3) * 32;
    float* Yb = out + (size_t)b * NC * NT;

#pragma unroll
    for (int mt = 0; mt < 4; mt++) {
        const int r0 = m0 + wm + mt * 16 + (lane >> 2);
        const float bv0 = o_b[r0], bv1 = o_b[r0 + 8];
#pragma unroll
        for (int nt = 0; nt < 4; nt++) {
            const int cn = n0 + wn + nt * 8 + (lane & 3) * 2;
            *(float2*)&Yb[(size_t)r0 * NT + cn] =
                make_float2(acc[mt][nt][0] + bv0, acc[mt][nt][1] + bv0);
            *(float2*)&Yb[(size_t)(r0 + 8) * NT + cn] =
                make_float2(acc[mt][nt][2] + bv1, acc[mt][nt][3] + bv1);
        }
    }
}

// ---------------------------------------------------------------------------
// Register-resident FA2 attention, fp16 hi-only (Q, K, V, P all fp16).
// Grid (T/128, NH, NB), 256 threads (8 warps). Each warp: 16 query rows x
// all 64 keys per chunk. Softmax in registers via quad shuffles.
// SMEM: Q staged in first 16KB, then 2 x 16KB KV buffers (K 8KB | V 8KB).
// ---------------------------------------------------------------------------
#define KV_BUF 16384u
#define SMEM_ATT 32768

__global__ __launch_bounds__(256) void attn_mma_kernel()
{
    extern __shared__ char sm[];
    const uint32_t smb = smem_to_u32(sm);
    const int tid = threadIdx.x, wid = tid >> 5, lane = tid & 31;
    const int b = blockIdx.z, h = blockIdx.y;
    const int q0 = blockIdx.x * 128;
    const int z = b * NH + h;
    const int wm = wid * 16;

    // ---- stage Q (16KB), load frags, free smem ----
    {
        const __half* qhp = g_qkvh + QOFF + ((size_t)z * NT + q0) * 64;
        for (int idx = tid; idx < 1024; idx += 256) {
            const int row = idx >> 3, v = idx & 7;
            const uint32_t d = row * 128 + ((v * 16) ^ ((row & 7) << 4));
            *(uint4*)(sm + d) = *((const uint4*)(qhp + row * 64) + v);
        }
    }
    __syncthreads();

    const int a_row = (lane & 7) + ((lane >> 3) & 1) * 8;
    const int a_cs  = (lane >> 4) & 1;
    uint32_t qh[4][4];
#pragma unroll
    for (int ks = 0; ks < 4; ks++) {
        const int r = wm + a_row;
        LDMX4(qh[ks],
              smb + r * 128 + ((uint32_t)(ks * 32 + a_cs * 16) ^ ((r & 7) << 4)));
    }
    __syncthreads();   // all warps done reading Q staging

    // ---- KV staging ----
    const __half* kh_g = g_qkvh + KOFF + (size_t)z * NT * 64;
    const __half* vh_g = g_qkvh + VOFF + (size_t)z * NT * 64;

    auto stageKV = [&](int ch, int buf) {
        const uint32_t base = smb + buf * KV_BUF;
        const int k0 = ch * 64;
#pragma unroll
        for (int it = 0; it < 2; it++) {
            const int idx = tid + it * 256;       // 0..511
            const int row = idx >> 3, v = idx & 7;
            const uint32_t d = row * 128 + ((v * 16) ^ ((row & 7) << 4));
            const size_t go = (size_t)(k0 + row) * 64 + v * 8;
            CP_ASYNC16(base + d,        kh_g + go);
            CP_ASYNC16(base + 8192 + d, vh_g + go);
        }
        CP_COMMIT();
    };
    stageKV(0, 0);

    float m0 = -CUDART_INF_F, m1 = -CUDART_INF_F;
    float l0 = 0.f, l1 = 0.f;
    float oacc[8][4];
#pragma unroll
    for (int nt = 0; nt < 8; nt++)
#pragma unroll
        for (int i = 0; i < 4; i++) oacc[nt][i] = 0.f;

    const int b_row = lane & 7;
    const int b_cs  = (lane >> 3) & 1;

    for (int ch = 0; ch < 16; ch++) {
        if (ch < 15) { stageKV(ch + 1, (ch + 1) & 1); CP_WAIT(1); }
        else         { CP_WAIT(0); }
        __syncthreads();
        const uint32_t base = smb + (ch & 1) * KV_BUF;

        // ---- S = Q K^T ----
        float sacc[8][4];
#pragma unroll
        for (int nt = 0; nt < 8; nt++)
#pragma unroll
            for (int i = 0; i < 4; i++) sacc[nt][i] = 0.f;

#pragma unroll
        for (int ks = 0; ks < 4; ks++) {
#pragma unroll
            for (int nt = 0; nt < 8; nt++) {
                uint32_t bh[2];
                const int r = nt * 8 + b_row;
                LDMX2(bh, base + r * 128 +
                          ((uint32_t)(ks * 32 + b_cs * 16) ^ ((r & 7) << 4)));
                mma_f16(sacc[nt], qh[ks], bh);
            }
        }

        // ---- in-register online softmax ----
        float mx0 = -CUDART_INF_F, mx1 = -CUDART_INF_F;
#pragma unroll
        for (int nt = 0; nt < 8; nt++) {
            sacc[nt][0] *= 0.125f; sacc[nt][1] *= 0.125f;
            sacc[nt][2] *= 0.125f; sacc[nt][3] *= 0.125f;
            mx0 = fmaxf(mx0, fmaxf(sacc[nt][0], sacc[nt][1]));
            mx1 = fmaxf(mx1, fmaxf(sacc[nt][2], sacc[nt][3]));
        }
        mx0 = fmaxf(mx0, __shfl_xor_sync(0xffffffffu, mx0, 1));
        mx0 = fmaxf(mx0, __shfl_xor_sync(0xffffffffu, mx0, 2));
        mx1 = fmaxf(mx1, __shfl_xor_sync(0xffffffffu, mx1, 1));
        mx1 = fmaxf(mx1, __shfl_xor_sync(0xffffffffu, mx1, 2));
        const float mn0 = fmaxf(m0, mx0), mn1 = fmaxf(m1, mx1);
        const float al0 = __expf(m0 - mn0), al1 = __expf(m1 - mn1);
        m0 = mn0; m1 = mn1;
        float ls0 = 0.f, ls1 = 0.f;
#pragma unroll
        for (int nt = 0; nt < 8; nt++) {
            sacc[nt][0] = __expf(sacc[nt][0] - mn0);
            sacc[nt][1] = __expf(sacc[nt][1] - mn0);
            sacc[nt][2] = __expf(sacc[nt][2] - mn1);
            sacc[nt][3] = __expf(sacc[nt][3] - mn1);
            ls0 += sacc[nt][0] + sacc[nt][1];
            ls1 += sacc[nt][2] + sacc[nt][3];
        }
        ls0 += __shfl_xor_sync(0xffffffffu, ls0, 1);
        ls0 += __shfl_xor_sync(0xffffffffu, ls0, 2);
        ls1 += __shfl_xor_sync(0xffffffffu, ls1, 1);
        ls1 += __shfl_xor_sync(0xffffffffu, ls1, 2);
        l0 = l0 * al0 + ls0;
        l1 = l1 * al1 + ls1;
#pragma unroll
        for (int nt = 0; nt < 8; nt++) {
            oacc[nt][0] *= al0; oacc[nt][1] *= al0;
            oacc[nt][2] *= al1; oacc[nt][3] *= al1;
        }

        // ---- O += P V (P packed to fp16 in registers) ----
#pragma unroll
        for (int ksp = 0; ksp < 4; ksp++) {
            uint32_t ph[4];
            ph[0] = pack2h(sacc[2 * ksp][0],     sacc[2 * ksp][1]);
            ph[1] = pack2h(sacc[2 * ksp][2],     sacc[2 * ksp][3]);
            ph[2] = pack2h(sacc[2 * ksp + 1][0], sacc[2 * ksp + 1][1]);
            ph[3] = pack2h(sacc[2 * ksp + 1][2], sacc[2 * ksp + 1][3]);
            const int k = ksp * 16 + (lane & 15);
#pragma unroll
            for (int nt = 0; nt < 8; nt++) {
                uint32_t vh[2];
                LDMX2T(vh, base + 8192 + k * 128 +
                           ((uint32_t)(nt * 16) ^ ((k & 7) << 4)));
                mma_f16(oacc[nt], ph, vh);
            }
        }
        __syncthreads();   // compute done before next stage overwrites
    }

    // ---- epilogue: normalize, write fp16 to att region ----
    const float il0 = 1.f / l0, il1 = 1.f / l1;
    const int r = wm + (lane >> 2);
    const size_t rowo = ATTOFF + (size_t)b * (NC * NT) +
                        (size_t)(q0 + r) * NC + h * 64;
#pragma unroll
    for (int nt = 0; nt < 8; nt++) {
        const int d = nt * 8 + (lane & 3) * 2;
        *(__half2*)(g_a_h + rowo + d) = __halves2half2(
            __float2half(oacc[nt][0] * il0), __float2half(oacc[nt][1] * il0));
        *(__half2*)(g_a_h + rowo + 8 * NC + d) = __halves2half2(
            __float2half(oacc[nt][2] * il1), __float2half(oacc[nt][3] * il1));
    }
}

// ---------------------------------------------------------------------------
extern "C" void kernel_launch(void* const* d_in, const int* in_sizes, int n_in,
                              void* d_out, int out_size)
{
    const float* x    = (const float*)d_in[0];
    const float* c    = (const float*)d_in[1];
    const float* q_w  = (const float*)d_in[2];
    const float* q_b  = (const float*)d_in[3];
    const float* kv_w = (const float*)d_in[4];
    const float* kv_b = (const float*)d_in[5];
    const float* o_w  = (const float*)d_in[6];
    const float* o_b  = (const float*)d_in[7];
    float* out = (float*)d_out;

    static bool attr_done = false;
    if (!attr_done) {
        cudaFuncSetAttribute(qkv_gemm_kernel, cudaFuncAttributeMaxDynamicSharedMemorySize, SMEM_QKV);
        cudaFuncSetAttribute(o_gemm_kernel, cudaFuncAttributeMaxDynamicSharedMemorySize, SMEM_OG);
        cudaFuncSetAttribute(attn_mma_kernel, cudaFuncAttributeMaxDynamicSharedMemorySize, SMEM_ATT);
        attr_done = true;
    }

    // Convert all weights to fp16 (one launch)
    conv_w_kernel<<<1024, 256>>>(q_w, kv_w, o_w);
    // Fused transpose of x and c to [T][C] fp16
    tsplit2_kernel<<<dim3(32, 32, 2 * NB), dim3(32, 8)>>>(x, c);
    // Fused q+kv projection with RoPE epilogue (writes g_qkvh directly)
    qkv_gemm_kernel<<<dim3(8, 24, NB), 256, SMEM_QKV>>>(q_b, kv_b);
    // register-resident FA2 attention (writes fp16 att activations)
    attn_mma_kernel<<<dim3(NT / 128, NH, NB), 256, SMEM_ATT>>>();
    // out = o_w @ att + o_b
    o_gemm_kernel<<<dim3(8, 8, NB), 256, SMEM_OG>>>(o_b, out);
}

// round 12
// speedup vs baseline: 7.6771x; 1.0678x over previous
#include <cuda_runtime.h>
#include <cuda_fp16.h>
#include <math_constants.h>
#include <cstdint>

#define NB 4
#define NC 1024
#define NT 1024
#define NH 16
#define NDH 64
#define KDIM 1024

// ---------------------------------------------------------------------------
// Scratch (__device__ globals; allocation-free)
// ---------------------------------------------------------------------------
// Weights fp16: [q(1M) | kv(2M) | o(1M)] elems
__device__ __align__(16) __half g_w_hi[4 * 1024 * 1024];
// Activations fp16, [T][C] rows: [x(4M) | c(4M) | att(4M)] elems
__device__ __align__(16) __half g_a_h[12 * 1024 * 1024];
// RoPE'd q/k/v fp16, [b][h][t][64] rows: [q(4M) | k(4M) | v(4M)]
// (q pre-scaled by 1/8 = softmax scale; exact power of two)
__device__ __align__(16) __half g_qkvh[12 * 1024 * 1024];

#define QOFF ((size_t)0)
#define KOFF ((size_t)4 * 1024 * 1024)
#define VOFF ((size_t)8 * 1024 * 1024)
#define XOFF ((size_t)0)
#define COFF ((size_t)4 * 1024 * 1024)
#define ATTOFF ((size_t)8 * 1024 * 1024)

// ---------------------------------------------------------------------------
// Base-ISA tensor helpers (sm_80+ features; compile for plain sm_100)
// ---------------------------------------------------------------------------
__device__ __forceinline__ uint32_t smem_to_u32(const void* p) {
    uint32_t a;
    asm("{ .reg .u64 t; cvta.to.shared.u64 t, %1; cvt.u32.u64 %0, t; }"
        : "=r"(a) : "l"(p));
    return a;
}
#define CP_ASYNC16(dst, src) \
    asm volatile("cp.async.cg.shared.global [%0], [%1], 16;" \
        :: "r"(dst), "l"(src) : "memory")
#define CP_COMMIT() asm volatile("cp.async.commit_group;" ::: "memory")
#define CP_WAIT(n)  asm volatile("cp.async.wait_group %0;" :: "n"(n) : "memory")
#define LDMX4(r, addr) \
    asm volatile("ldmatrix.sync.aligned.m8n8.x4.shared.b16 {%0,%1,%2,%3}, [%4];" \
        : "=r"((r)[0]), "=r"((r)[1]), "=r"((r)[2]), "=r"((r)[3]) : "r"(addr))
#define LDMX4T(r, addr) \
    asm volatile("ldmatrix.sync.aligned.m8n8.x4.trans.shared.b16 {%0,%1,%2,%3}, [%4];" \
        : "=r"((r)[0]), "=r"((r)[1]), "=r"((r)[2]), "=r"((r)[3]) : "r"(addr))

__device__ __forceinline__ void mma_f16(float* c, const uint32_t* a,
                                        const uint32_t* b) {
    asm volatile(
        "mma.sync.aligned.m16n8k16.row.col.f32.f16.f16.f32 "
        "{%0,%1,%2,%3}, {%4,%5,%6,%7}, {%8,%9}, {%0,%1,%2,%3};"
        : "+f"(c[0]), "+f"(c[1]), "+f"(c[2]), "+f"(c[3])
        : "r"(a[0]), "r"(a[1]), "r"(a[2]), "r"(a[3]), "r"(b[0]), "r"(b[1]));
}

__device__ __forceinline__ uint32_t pack2h(float a, float b) {
    __half2 h = __halves2half2(__float2half(a), __float2half(b));
    return *(uint32_t*)&h;
}

// ---------------------------------------------------------------------------
// Weight convert (all three in one launch): fp32 -> fp16
// ---------------------------------------------------------------------------
__global__ __launch_bounds__(256) void conv_w_kernel(
    const float* __restrict__ qw, const float* __restrict__ kvw,
    const float* __restrict__ ow)
{
    const int stride = gridDim.x * blockDim.x;
    const int M1 = 1024 * 1024, M3 = 3 * 1024 * 1024, M4 = 4 * 1024 * 1024;
    for (int i = blockIdx.x * blockDim.x + threadIdx.x; i < M4; i += stride) {
        float v;
        if (i < M1)      v = qw[i];
        else if (i < M3) v = kvw[i - M1];
        else             v = ow[i - M3];
        g_w_hi[i] = __float2half(v);
    }
}

// ---------------------------------------------------------------------------
// Fused activation transpose: x,c [C][T] fp32 -> [T][C] fp16, half2 stores.
// Tile 64c x 32t. Grid (32, 16, 8): z<4 -> x batch z; else c batch z-4.
// ---------------------------------------------------------------------------
__global__ __launch_bounds__(256) void tsplit2_kernel(
    const float* __restrict__ x, const float* __restrict__ c)
{
    __shared__ float tile[64][33];
    const int z = blockIdx.z;
    const float* src = (z < 4) ? x + (size_t)z * NC * NT
                               : c + (size_t)(z - 4) * NC * NT;
    const size_t db = (z < 4) ? XOFF + (size_t)z * NC * NT
                              : COFF + (size_t)(z - 4) * NC * NT;
    const int t0 = blockIdx.x * 32, c0 = blockIdx.y * 64;
    const int tx = threadIdx.x, ty = threadIdx.y;
#pragma unroll
    for (int i = 0; i < 8; i++)
        tile[ty + 8 * i][tx] = src[(size_t)(c0 + ty + 8 * i) * NT + t0 + tx];
    __syncthreads();
#pragma unroll
    for (int i = 0; i < 4; i++) {
        const int t = t0 + ty + 8 * i;
        __half2 h = __halves2half2(__float2half(tile[2 * tx][ty + 8 * i]),
                                   __float2half(tile[2 * tx + 1][ty + 8 * i]));
        *(__half2*)&g_a_h[db + (size_t)t * NC + c0 + 2 * tx] = h;
    }
}

// ---------------------------------------------------------------------------
// fp16 GEMM mainloop: acc = W[m0..][.] * X[n0..][.]^T
// 128x128 CTA tile, 8 warps, K-chunk 64, cp.async double buffer.
// B loaded in n16 pairs via ldmatrix.x4.
// ---------------------------------------------------------------------------
#define BUF_BYTES 32768u
#define OFF_B 16384u

__device__ __forceinline__ void gemm_mainloop(
    const __half* __restrict__ Wh, const __half* __restrict__ Xh,
    char* sm, int m0, int n0, float acc[4][4][4])
{
    const uint32_t smb = smem_to_u32(sm);
    const int tid = threadIdx.x;
    const int wid = tid >> 5, lane = tid & 31;
    const int wm = (wid >> 2) * 64;
    const int wn = (wid & 3) * 32;

#pragma unroll
    for (int mt = 0; mt < 4; mt++)
#pragma unroll
        for (int nt = 0; nt < 4; nt++)
#pragma unroll
            for (int i = 0; i < 4; i++) acc[mt][nt][i] = 0.f;

    auto stage = [&](int ch, int buf) {
        const uint32_t base = smb + buf * BUF_BYTES;
        const int k0 = ch * 64;
#pragma unroll
        for (int it = 0; it < 4; it++) {
            const int idx = tid + it * 256;
            const int row = idx >> 3, v = idx & 7;
            const uint32_t dst = base + row * 128 + ((v * 16) ^ ((row & 7) << 4));
            CP_ASYNC16(dst,         Wh + (size_t)(m0 + row) * KDIM + k0 + v * 8);
            CP_ASYNC16(dst + OFF_B, Xh + (size_t)(n0 + row) * KDIM + k0 + v * 8);
        }
        CP_COMMIT();
    };

    stage(0, 0);

    const int a_row_in = (lane & 7) + ((lane >> 3) & 1) * 8;
    const int a_colsel = (lane >> 4) & 1;
    // x4 pair-load lane mapping for B: matrices {n0..7 k-lo, n0..7 k-hi,
    // n8..15 k-lo, n8..15 k-hi}
    const int b_row_in = (lane & 7) + ((lane >> 4) << 3);
    const int b_colsel = (lane >> 3) & 1;

    for (int ch = 0; ch < 16; ch++) {
        if (ch < 15) { stage(ch + 1, (ch + 1) & 1); CP_WAIT(1); }
        else         { CP_WAIT(0); }
        __syncthreads();
        const uint32_t base = smb + (ch & 1) * BUF_BYTES;

#pragma unroll
        for (int ks = 0; ks < 4; ks++) {
            uint32_t ah[4][4];
#pragma unroll
            for (int mt = 0; mt < 4; mt++) {
                const int r = wm + mt * 16 + a_row_in;
                const uint32_t col = (uint32_t)(ks * 32 + a_colsel * 16);
                LDMX4(ah[mt], base + r * 128 + (col ^ ((r & 7) << 4)));
            }
            uint32_t bh[2][4];
#pragma unroll
            for (int ntp = 0; ntp < 2; ntp++) {
                const int r = wn + ntp * 16 + b_row_in;
                const uint32_t col = (uint32_t)(ks * 32 + b_colsel * 16);
                LDMX4(bh[ntp], base + OFF_B + r * 128 + (col ^ ((r & 7) << 4)));
            }
#pragma unroll
            for (int mt = 0; mt < 4; mt++)
#pragma unroll
                for (int nt = 0; nt < 4; nt++)
                    mma_f16(acc[mt][nt], ah[mt], bh[nt >> 1] + (nt & 1) * 2);
        }
        __syncthreads();
    }
}

// ---------------------------------------------------------------------------
// Fused q+kv projection with RoPE + fp16 epilogue writing [b][h][t][64].
// Grid (8, 24, NB): yb<8 -> q (x input); yb>=8 -> kv (c input).
// Q additionally pre-scaled by 1/8 (softmax scale; exact pow2).
// ---------------------------------------------------------------------------
#define SMEM_QKV 65536

__global__ __launch_bounds__(256) void qkv_gemm_kernel(
    const float* __restrict__ q_b, const float* __restrict__ kv_b)
{
    extern __shared__ char sm[];
    const int b = blockIdx.z, yb = blockIdx.y;
    const int n0 = blockIdx.x * 128;
    const bool isQ = (yb < 8);
    const int m0 = isQ ? yb * 128 : (yb - 8) * 128;
    const __half* W = isQ ? g_w_hi : g_w_hi + 1024 * 1024;
    const __half* X = g_a_h + (isQ ? XOFF : COFF) + (size_t)b * NC * NT;
    const float* bias = isQ ? q_b : kv_b;

    float acc[4][4][4];
    gemm_mainloop(W, X, sm, m0, n0, acc);

    const int tid = threadIdx.x, wid = tid >> 5, lane = tid & 31;
    const int wm = (wid >> 2) * 64, wn = (wid & 3) * 32;
    const bool isV = (!isQ) && (m0 >= 1024);

    // bias (before RoPE, matching reference)
#pragma unroll
    for (int mt = 0; mt < 4; mt++) {
        const int r0 = wm + mt * 16 + (lane >> 2);
        const float b0 = bias[m0 + r0], b1 = bias[m0 + r0 + 8];
#pragma unroll
        for (int nt = 0; nt < 4; nt++) {
            acc[mt][nt][0] += b0; acc[mt][nt][1] += b0;
            acc[mt][nt][2] += b1; acc[mt][nt][3] += b1;
        }
    }

    // RoPE on head dims [0,32): pair (j, j+16) = (acc[0], acc[1]) same thread
    if (!isV) {
        const float LN = 0.57564627324851145f;  // ln(10000)/16
        const int j0 = lane >> 2;
        const float th0 = __expf(-(float)j0 * LN);
        const float th1 = __expf(-(float)(j0 + 8) * LN);
#pragma unroll
        for (int nt = 0; nt < 4; nt++) {
#pragma unroll
            for (int i = 0; i < 4; i++) {
                const int t = n0 + wn + nt * 8 + (lane & 3) * 2 + (i & 1);
                const float th = (i >= 2) ? th1 : th0;
                float sn, cs;
                sincosf((float)t * th, &sn, &cs);
                const float a0 = acc[0][nt][i], a1 = acc[1][nt][i];
                acc[0][nt][i] = a0 * cs - a1 * sn;
                acc[1][nt][i] = a1 * cs + a0 * sn;
            }
        }
    }

    // Q pre-scale by softmax scale 1/8 (exact)
    const float qscale = isQ ? 0.125f : 1.0f;

    // stage [t][c] (pad 136) in smem as fp16
    __half* s_hi = (__half*)sm;
#pragma unroll
    for (int mt = 0; mt < 4; mt++) {
#pragma unroll
        for (int nt = 0; nt < 4; nt++) {
#pragma unroll
            for (int i = 0; i < 4; i++) {
                const int r = wm + mt * 16 + (lane >> 2) + ((i >> 1) << 3);
                const int col = wn + nt * 8 + (lane & 3) * 2 + (i & 1);
                s_hi[col * 136 + r] = __float2half(acc[mt][nt][i] * qscale);
            }
        }
    }
    __syncthreads();

    // coalesced copy-out: 128 t x 128 c (2 heads x 64)
    const size_t roff = isQ ? QOFF : (m0 < 1024 ? KOFF : VOFF);
    const int hd0 = (m0 & 1023) >> 6;
    const int z0 = b * NH + hd0;
    for (int idx = tid; idx < 128 * 16; idx += 256) {
        const int t = idx >> 4, u = idx & 15;
        const int cc = u * 8;
        const int hd = cc >> 6, cl = cc & 63;
        const size_t go = ((size_t)(z0 + hd) * NT + (n0 + t)) * 64 + cl;
        *(uint4*)(g_qkvh + roff + go) = *(uint4*)(s_hi + t * 136 + cc);
    }
}

// ---------------------------------------------------------------------------
// Output projection: out = o_w @ att + o_b (fp32 out)
// ---------------------------------------------------------------------------
#define SMEM_OG (2 * 32768)

__global__ __launch_bounds__(256) void o_gemm_kernel(
    const float* __restrict__ o_b, float* __restrict__ out)
{
    extern __shared__ char sm[];
    const int b = blockIdx.z;
    const int m0 = blockIdx.y * 128, n0 = blockIdx.x * 128;

    float acc[4][4][4];
    gemm_mainloop(g_w_hi + 3 * 1024 * 1024,
                  g_a_h + ATTOFF + (size_t)b * NC * NT, sm, m0, n0, acc);

    const int tid = threadIdx.x, wid = tid >> 5, lane = tid & 31;
    const int wm = (wid >> 2) * 64, wn = (wid & 3) * 32;
    float* Yb = out + (size_t)b * NC * NT;

#pragma unroll
    for (int mt = 0; mt < 4; mt++) {
        const int r0 = m0 + wm + mt * 16 + (lane >> 2);
        const float bv0 = o_b[r0], bv1 = o_b[r0 + 8];
#pragma unroll
        for (int nt = 0; nt < 4; nt++) {
            const int cn = n0 + wn + nt * 8 + (lane & 3) * 2;
            *(float2*)&Yb[(size_t)r0 * NT + cn] =
                make_float2(acc[mt][nt][0] + bv0, acc[mt][nt][1] + bv0);
            *(float2*)&Yb[(size_t)(r0 + 8) * NT + cn] =
                make_float2(acc[mt][nt][2] + bv1, acc[mt][nt][3] + bv1);
        }
    }
}

// ---------------------------------------------------------------------------
// Register-resident FA2 attention, fp16. Q pre-scaled by 1/8.
// Grid (T/128, NH, NB), 256 threads (8 warps), 16 query rows/warp.
// K and V loaded in n16 pairs via ldmatrix.x4(.trans). exp2-based softmax.
// SMEM: Q staged in first 16KB, then 2 x 16KB KV buffers (K 8KB | V 8KB).
// ---------------------------------------------------------------------------
#define KV_BUF 16384u
#define SMEM_ATT 32768
#define LOG2E 1.4426950408889634f

__global__ __launch_bounds__(256) void attn_mma_kernel()
{
    extern __shared__ char sm[];
    const uint32_t smb = smem_to_u32(sm);
    const int tid = threadIdx.x, wid = tid >> 5, lane = tid & 31;
    const int b = blockIdx.z, h = blockIdx.y;
    const int q0 = blockIdx.x * 128;
    const int z = b * NH + h;
    const int wm = wid * 16;

    // ---- stage Q (16KB), load frags, free smem ----
    {
        const __half* qhp = g_qkvh + QOFF + ((size_t)z * NT + q0) * 64;
        for (int idx = tid; idx < 1024; idx += 256) {
            const int row = idx >> 3, v = idx & 7;
            const uint32_t d = row * 128 + ((v * 16) ^ ((row & 7) << 4));
            *(uint4*)(sm + d) = *((const uint4*)(qhp + row * 64) + v);
        }
    }
    __syncthreads();

    const int a_row = (lane & 7) + ((lane >> 3) & 1) * 8;
    const int a_cs  = (lane >> 4) & 1;
    uint32_t qh[4][4];
#pragma unroll
    for (int ks = 0; ks < 4; ks++) {
        const int r = wm + a_row;
        LDMX4(qh[ks],
              smb + r * 128 + ((uint32_t)(ks * 32 + a_cs * 16) ^ ((r & 7) << 4)));
    }
    __syncthreads();   // all warps done reading Q staging

    // ---- KV staging ----
    const __half* kh_g = g_qkvh + KOFF + (size_t)z * NT * 64;
    const __half* vh_g = g_qkvh + VOFF + (size_t)z * NT * 64;

    auto stageKV = [&](int ch, int buf) {
        const uint32_t base = smb + buf * KV_BUF;
        const int k0 = ch * 64;
#pragma unroll
        for (int it = 0; it < 2; it++) {
            const int idx = tid + it * 256;       // 0..511
            const int row = idx >> 3, v = idx & 7;
            const uint32_t d = row * 128 + ((v * 16) ^ ((row & 7) << 4));
            const size_t go = (size_t)(k0 + row) * 64 + v * 8;
            CP_ASYNC16(base + d,        kh_g + go);
            CP_ASYNC16(base + 8192 + d, vh_g + go);
        }
        CP_COMMIT();
    };
    stageKV(0, 0);

    float m0 = -CUDART_INF_F, m1 = -CUDART_INF_F;
    float l0 = 0.f, l1 = 0.f;
    float oacc[8][4];
#pragma unroll
    for (int nt = 0; nt < 8; nt++)
#pragma unroll
        for (int i = 0; i < 4; i++) oacc[nt][i] = 0.f;

    // x4 pair-load lane mappings
    const int bk_row = (lane & 7) + ((lane >> 4) << 3);   // K: n-row within pair
    const int bk_cs  = (lane >> 3) & 1;                   // K: k-half
    const int vk_row = (lane & 7) + ((lane >> 3) & 1) * 8; // V: k-row within 16
    const int v_cs   = (lane >> 4) & 1;                   // V: n-half (16B)

    for (int ch = 0; ch < 16; ch++) {
        if (ch < 15) { stageKV(ch + 1, (ch + 1) & 1); CP_WAIT(1); }
        else         { CP_WAIT(0); }
        __syncthreads();
        const uint32_t base = smb + (ch & 1) * KV_BUF;

        // ---- S = Q K^T (K in n16 pairs) ----
        float sacc[8][4];
#pragma unroll
        for (int nt = 0; nt < 8; nt++)
#pragma unroll
            for (int i = 0; i < 4; i++) sacc[nt][i] = 0.f;

#pragma unroll
        for (int ks = 0; ks < 4; ks++) {
#pragma unroll
            for (int ntp = 0; ntp < 4; ntp++) {
                uint32_t bb[4];
                const int r = ntp * 16 + bk_row;
                LDMX4(bb, base + r * 128 +
                          ((uint32_t)(ks * 32 + bk_cs * 16) ^ ((r & 7) << 4)));
                mma_f16(sacc[2 * ntp],     qh[ks], bb);
                mma_f16(sacc[2 * ntp + 1], qh[ks], bb + 2);
            }
        }

        // ---- in-register online softmax (exp2-based; scores pre-scaled) ----
        float mx0 = -CUDART_INF_F, mx1 = -CUDART_INF_F;
#pragma unroll
        for (int nt = 0; nt < 8; nt++) {
            mx0 = fmaxf(mx0, fmaxf(sacc[nt][0], sacc[nt][1]));
            mx1 = fmaxf(mx1, fmaxf(sacc[nt][2], sacc[nt][3]));
        }
        mx0 = fmaxf(mx0, __shfl_xor_sync(0xffffffffu, mx0, 1));
        mx0 = fmaxf(mx0, __shfl_xor_sync(0xffffffffu, mx0, 2));
        mx1 = fmaxf(mx1, __shfl_xor_sync(0xffffffffu, mx1, 1));
        mx1 = fmaxf(mx1, __shfl_xor_sync(0xffffffffu, mx1, 2));
        const float mn0 = fmaxf(m0, mx0), mn1 = fmaxf(m1, mx1);
        const float al0 = exp2f((m0 - mn0) * LOG2E);
        const float al1 = exp2f((m1 - mn1) * LOG2E);
        m0 = mn0; m1 = mn1;
        const float c0 = mn0 * LOG2E, c1 = mn1 * LOG2E;
        float ls0 = 0.f, ls1 = 0.f;
#pragma unroll
        for (int nt = 0; nt < 8; nt++) {
            sacc[nt][0] = exp2f(fmaf(sacc[nt][0], LOG2E, -c0));
            sacc[nt][1] = exp2f(fmaf(sacc[nt][1], LOG2E, -c0));
            sacc[nt][2] = exp2f(fmaf(sacc[nt][2], LOG2E, -c1));
            sacc[nt][3] = exp2f(fmaf(sacc[nt][3], LOG2E, -c1));
            ls0 += sacc[nt][0] + sacc[nt][1];
            ls1 += sacc[nt][2] + sacc[nt][3];
        }
        ls0 += __shfl_xor_sync(0xffffffffu, ls0, 1);
        ls0 += __shfl_xor_sync(0xffffffffu, ls0, 2);
        ls1 += __shfl_xor_sync(0xffffffffu, ls1, 1);
        ls1 += __shfl_xor_sync(0xffffffffu, ls1, 2);
        l0 = l0 * al0 + ls0;
        l1 = l1 * al1 + ls1;
#pragma unroll
        for (int nt = 0; nt < 8; nt++) {
            oacc[nt][0] *= al0; oacc[nt][1] *= al0;
            oacc[nt][2] *= al1; oacc[nt][3] *= al1;
        }

        // ---- O += P V (P packed in regs; V in n16 pairs via x4.trans) ----
#pragma unroll
        for (int ksp = 0; ksp < 4; ksp++) {
            uint32_t ph[4];
            ph[0] = pack2h(sacc[2 * ksp][0],     sacc[2 * ksp][1]);
            ph[1] = pack2h(sacc[2 * ksp][2],     sacc[2 * ksp][3]);
            ph[2] = pack2h(sacc[2 * ksp + 1][0], sacc[2 * ksp + 1][1]);
            ph[3] = pack2h(sacc[2 * ksp + 1][2], sacc[2 * ksp + 1][3]);
            const int k = ksp * 16 + vk_row;
#pragma unroll
            for (int ntp = 0; ntp < 4; ntp++) {
                uint32_t vv[4];
                const uint32_t col = (uint32_t)(ntp * 32 + v_cs * 16);
                LDMX4T(vv, base + 8192 + k * 128 + (col ^ ((k & 7) << 4)));
                mma_f16(oacc[2 * ntp],     ph, vv);
                mma_f16(oacc[2 * ntp + 1], ph, vv + 2);
            }
        }
        __syncthreads();   // compute done before next stage overwrites
    }

    // ---- epilogue: normalize, write fp16 to att region ----
    const float il0 = 1.f / l0, il1 = 1.f / l1;
    const int r = wm + (lane >> 2);
    const size_t rowo = ATTOFF + (size_t)b * (NC * NT) +
                        (size_t)(q0 + r) * NC + h * 64;
#pragma unroll
    for (int nt = 0; nt < 8; nt++) {
        const int d = nt * 8 + (lane & 3) * 2;
        *(__half2*)(g_a_h + rowo + d) = __halves2half2(
            __float2half(oacc[nt][0] * il0), __float2half(oacc[nt][1] * il0));
        *(__half2*)(g_a_h + rowo + 8 * NC + d) = __halves2half2(
            __float2half(oacc[nt][2] * il1), __float2half(oacc[nt][3] * il1));
    }
}

// ---------------------------------------------------------------------------
extern "C" void kernel_launch(void* const* d_in, const int* in_sizes, int n_in,
                              void* d_out, int out_size)
{
    const float* x    = (const float*)d_in[0];
    const float* c    = (const float*)d_in[1];
    const float* q_w  = (const float*)d_in[2];
    const float* q_b  = (const float*)d_in[3];
    const float* kv_w = (const float*)d_in[4];
    const float* kv_b = (const float*)d_in[5];
    const float* o_w  = (const float*)d_in[6];
    const float* o_b  = (const float*)d_in[7];
    float* out = (float*)d_out;

    static bool attr_done = false;
    if (!attr_done) {
        cudaFuncSetAttribute(qkv_gemm_kernel, cudaFuncAttributeMaxDynamicSharedMemorySize, SMEM_QKV);
        cudaFuncSetAttribute(o_gemm_kernel, cudaFuncAttributeMaxDynamicSharedMemorySize, SMEM_OG);
        cudaFuncSetAttribute(attn_mma_kernel, cudaFuncAttributeMaxDynamicSharedMemorySize, SMEM_ATT);
        attr_done = true;
    }

    // Convert all weights to fp16 (one launch)
    conv_w_kernel<<<1024, 256>>>(q_w, kv_w, o_w);
    // Fused transpose of x and c to [T][C] fp16
    tsplit2_kernel<<<dim3(32, 16, 2 * NB), dim3(32, 8)>>>(x, c);
    // Fused q+kv projection with RoPE epilogue (Q pre-scaled by 1/8)
    qkv_gemm_kernel<<<dim3(8, 24, NB), 256, SMEM_QKV>>>(q_b, kv_b);
    // register-resident FA2 attention (writes fp16 att activations)
    attn_mma_kernel<<<dim3(NT / 128, NH, NB), 256, SMEM_ATT>>>();
    // out = o_w @ att + o_b
    o_gemm_kernel<<<dim3(8, 8, NB), 256, SMEM_OG>>>(o_b, out);
}